// round 1
// baseline (speedup 1.0000x reference)
#include <cuda_runtime.h>
#include <math.h>

// ---------------- problem constants ----------------
#define DIM   256
#define HEADS 8
#define HD    32
#define B_    2
#define T_    8
#define H_    56
#define W_    56
#define WT    2
#define WH    7
#define WW    7
#define STs   1
#define SHs   3
#define SWs   3
#define NTOK  (B_*T_*H_*W_)   // 50176
#define BW_   512             // B * nW = 2*256
#define N_    98
#define HID   1024

// ---------------- scratch (device globals; no allocation allowed) ----------
__device__ float g_xw [BW_*N_*DIM];     // LN1+roll+partitioned windows
__device__ float g_qkv[BW_*N_*3*DIM];   // qkv
__device__ float g_att[BW_*N_*DIM];     // attention out (Bw,N,C)
__device__ float g_x2 [NTOK*DIM];       // residual-1 result
__device__ float g_hn [NTOK*DIM];       // LN2 output
__device__ float g_h3 [NTOK*HID];       // fc1+gelu output

// ---------------- LN kernel (mode 0: LN1 + roll + window partition; mode 1: plain LN2)
__global__ void ln_kernel(const float* __restrict__ src, float* __restrict__ dst,
                          const float* __restrict__ w, const float* __restrict__ b,
                          int mode) {
    int warp = threadIdx.x >> 5, lane = threadIdx.x & 31;
    int row = blockIdx.x * 8 + warp;            // token index, < 50176
    const float* sr = src + (size_t)row * DIM;
    float4 v0 = *(const float4*)(sr + lane * 4);
    float4 v1 = *(const float4*)(sr + 128 + lane * 4);
    float s  = v0.x + v0.y + v0.z + v0.w + v1.x + v1.y + v1.z + v1.w;
    float ss = v0.x*v0.x + v0.y*v0.y + v0.z*v0.z + v0.w*v0.w
             + v1.x*v1.x + v1.y*v1.y + v1.z*v1.z + v1.w*v1.w;
    #pragma unroll
    for (int o = 16; o > 0; o >>= 1) {
        s  += __shfl_xor_sync(0xffffffffu, s, o);
        ss += __shfl_xor_sync(0xffffffffu, ss, o);
    }
    float mean = s * (1.0f / 256.0f);
    float var  = ss * (1.0f / 256.0f) - mean * mean;
    float inv  = rsqrtf(var + 1e-5f);

    size_t drow = row;
    if (mode == 0) {
        // token -> (b,t,h,w)
        int bb = row / (T_*H_*W_);
        int r2 = row % (T_*H_*W_);
        int t = r2 / (H_*W_);
        int r3 = r2 % (H_*W_);
        int h = r3 / W_, ww_ = r3 % W_;
        // roll by (-1,-3,-3): source (t,h,w) lands at (t-1, h-3, w-3) mod dims
        int t2 = t - STs; if (t2 < 0) t2 += T_;
        int h2 = h - SHs; if (h2 < 0) h2 += H_;
        int w2 = ww_ - SWs; if (w2 < 0) w2 += W_;
        int tw = t2 / WT, hw = h2 / WH, wwn = w2 / WW;
        int n = (t2 % WT) * 49 + (h2 % WH) * 7 + (w2 % WW);
        int bw = ((bb * 4 + tw) * 8 + hw) * 8 + wwn;
        drow = (size_t)bw * N_ + n;
    }
    float* dr = dst + drow * DIM;
    int c0 = lane * 4, c1 = 128 + lane * 4;
    float4 o0, o1;
    o0.x = (v0.x - mean) * inv * w[c0+0] + b[c0+0];
    o0.y = (v0.y - mean) * inv * w[c0+1] + b[c0+1];
    o0.z = (v0.z - mean) * inv * w[c0+2] + b[c0+2];
    o0.w = (v0.w - mean) * inv * w[c0+3] + b[c0+3];
    o1.x = (v1.x - mean) * inv * w[c1+0] + b[c1+0];
    o1.y = (v1.y - mean) * inv * w[c1+1] + b[c1+1];
    o1.z = (v1.z - mean) * inv * w[c1+2] + b[c1+2];
    o1.w = (v1.w - mean) * inv * w[c1+3] + b[c1+3];
    *(float4*)(dr + c0) = o0;
    *(float4*)(dr + c1) = o1;
}

// ---------------- tiled SGEMM: C[M,N] = A[M,K] @ B[N,K]^T (+ epilogues) -----
// EPI 0: + bias                        (qkv)
// EPI 1: + bias, GELU(exact)           (fc1)
// EPI 2: + bias, window-reverse + roll-back remap, += resid(x)   (proj)
// EPI 3: + bias, += resid (same row)   (fc2 -> final out)
template<int EPI>
__global__ void gemm64(const float* __restrict__ A, const float* __restrict__ Bm,
                       const float* __restrict__ bias, const float* __restrict__ resid,
                       float* __restrict__ C, int M, int N, int K) {
    __shared__ float As[16][64];
    __shared__ float Bs[16][64];
    int tid = threadIdx.x;
    int tx = tid & 15, ty = tid >> 4;
    int brow = blockIdx.y * 64;
    int bcol = blockIdx.x * 64;
    int lr = tid >> 2;          // 0..63
    int lk = (tid & 3) << 2;    // 0,4,8,12

    float acc[4][4] = {};
    const float* Ap = A + (size_t)(brow + lr) * K + lk;
    const float* Bp = Bm + (size_t)(bcol + lr) * K + lk;
    for (int k0 = 0; k0 < K; k0 += 16) {
        float4 a4 = *(const float4*)(Ap + k0);
        float4 b4 = *(const float4*)(Bp + k0);
        As[lk+0][lr] = a4.x; As[lk+1][lr] = a4.y; As[lk+2][lr] = a4.z; As[lk+3][lr] = a4.w;
        Bs[lk+0][lr] = b4.x; Bs[lk+1][lr] = b4.y; Bs[lk+2][lr] = b4.z; Bs[lk+3][lr] = b4.w;
        __syncthreads();
        #pragma unroll
        for (int k = 0; k < 16; k++) {
            float a[4], bb[4];
            #pragma unroll
            for (int i = 0; i < 4; i++) a[i]  = As[k][ty*4+i];
            #pragma unroll
            for (int j = 0; j < 4; j++) bb[j] = Bs[k][tx*4+j];
            #pragma unroll
            for (int i = 0; i < 4; i++)
                #pragma unroll
                for (int j = 0; j < 4; j++)
                    acc[i][j] = fmaf(a[i], bb[j], acc[i][j]);
        }
        __syncthreads();
    }

    #pragma unroll
    for (int i = 0; i < 4; i++) {
        int row = brow + ty*4 + i;
        size_t orow = row;
        if (EPI == 2) {
            // window row -> original token index (window reverse + roll back)
            int bw = row / N_, n = row % N_;
            int bb = bw >> 8, wrem = bw & 255;
            int tw = wrem >> 6, hw = (wrem >> 3) & 7, wwn = wrem & 7;
            int nt = n / 49, nr = n % 49;
            int t2 = tw*WT + nt, h2 = hw*WH + nr/7, w2 = wwn*WW + nr%7;
            int t = t2 + STs; if (t >= T_) t -= T_;
            int h = h2 + SHs; if (h >= H_) h -= H_;
            int ww_ = w2 + SWs; if (ww_ >= W_) ww_ -= W_;
            orow = ((size_t)((bb*T_ + t)*H_ + h))*W_ + ww_;
        }
        #pragma unroll
        for (int j = 0; j < 4; j++) {
            int col = bcol + tx*4 + j;
            float v = acc[i][j] + bias[col];
            if (EPI == 0) {
                C[(size_t)orow * N + col] = v;
            } else if (EPI == 1) {
                C[(size_t)orow * N + col] = 0.5f * v * (1.0f + erff(v * 0.70710678118654752f));
            } else if (EPI == 2) {
                size_t o = orow * DIM + col;
                C[o] = resid[o] + v;
            } else {
                size_t o = orow * (size_t)N + col;
                C[o] = resid[o] + v;
            }
        }
    }
}

// ---------------- attention: one block per (window, head) ------------------
__global__ void attn_kernel(const float* __restrict__ rpe) {
    extern __shared__ float sm[];
    float* qs = sm;                  // 98*32
    float* ks = sm + 98*32;          // 98*32
    float* vs = sm + 2*98*32;        // 98*32
    float* ps = sm + 3*98*32;        // 98*99 (stride 99, conflict-free)
    int*   tc = (int*)(ps + 98*99);  // 98 packed coords/region

    int bid  = blockIdx.x;
    int head = bid & 7;
    int bw   = bid >> 3;
    int wrem = bw & 255;
    int tw = wrem >> 6, hw = (wrem >> 3) & 7, wwn = wrem & 7;
    int tid = threadIdx.x;

    const float* base = g_qkv + ((size_t)bw * N_) * (3*DIM) + head * HD;
    for (int i = tid; i < N_*HD; i += 128) {
        int m = i >> 5, d = i & 31;
        size_t o = (size_t)m * (3*DIM) + d;
        qs[i] = base[o];
        ks[i] = base[o + DIM];
        vs[i] = base[o + 2*DIM];
    }
    if (tid < N_) {
        int t = tid / 49, rem = tid % 49, h = rem / 7, w = rem % 7;
        int gt = tw*WT + t, gh = hw*WH + h, gw = wwn*WW + w;
        int rt = (gt < T_-WT) ? 0 : ((gt < T_-STs) ? 1 : 2);
        int rh = (gh < H_-WH) ? 0 : ((gh < H_-SHs) ? 1 : 2);
        int rw = (gw < W_-WW) ? 0 : ((gw < W_-SWs) ? 1 : 2);
        tc[tid] = t | (h << 4) | (w << 8) | ((rt*9 + rh*3 + rw) << 12);
    }
    __syncthreads();

    if (tid < N_) {
        int r = tid;
        int pc = tc[r];
        int tr = pc & 15, hr = (pc >> 4) & 15, wr = (pc >> 8) & 15, regr = pc >> 12;
        float qreg[HD];
        const float* qrow = qs + r*HD;
        #pragma unroll
        for (int d = 0; d < HD; d++) qreg[d] = qrow[d] * 0.17677669529663687f; // 1/sqrt(32)

        float* prow = ps + r*99;
        float mx = -1e30f;
        for (int m = 0; m < N_; m++) {
            const float* krow = ks + m*HD;
            float s = 0.f;
            #pragma unroll
            for (int d = 0; d < HD; d++) s = fmaf(qreg[d], krow[d], s);
            int pm = tc[m];
            int idx = (tr - (pm & 15) + (WT-1)) * ((2*WH-1)*(2*WW-1))
                    + (hr - ((pm >> 4) & 15) + (WH-1)) * (2*WW-1)
                    + (wr - ((pm >> 8) & 15) + (WW-1));
            s += __ldg(&rpe[idx * HEADS + head]);
            if (regr != (pm >> 12)) s -= 100.0f;
            prow[m] = s;
            mx = fmaxf(mx, s);
        }
        float sum = 0.f;
        for (int m = 0; m < N_; m++) {
            float e = __expf(prow[m] - mx);
            prow[m] = e;
            sum += e;
        }
        float invs = 1.0f / sum;

        float* orow = g_att + ((size_t)(bw*N_ + r)) * DIM + head * HD;
        #pragma unroll
        for (int d0 = 0; d0 < HD; d0 += 8) {
            float acc[8] = {};
            for (int m = 0; m < N_; m++) {
                float p = prow[m];
                const float* vr = vs + m*HD + d0;
                #pragma unroll
                for (int j = 0; j < 8; j++) acc[j] = fmaf(p, vr[j], acc[j]);
            }
            #pragma unroll
            for (int j = 0; j < 8; j++) orow[d0 + j] = acc[j] * invs;
        }
    }
}

#define ATTN_SMEM ((3*98*32 + 98*99) * 4 + 98 * 4)

// ---------------- host launcher ---------------------------------------------
extern "C" void kernel_launch(void* const* d_in, const int* in_sizes, int n_in,
                              void* d_out, int out_size) {
    const float* x     = (const float*)d_in[0];
    const float* n1w   = (const float*)d_in[1];
    const float* n1b   = (const float*)d_in[2];
    const float* qkvw  = (const float*)d_in[3];
    const float* qkvb  = (const float*)d_in[4];
    const float* projw = (const float*)d_in[5];
    const float* projb = (const float*)d_in[6];
    const float* rpe   = (const float*)d_in[7];
    const float* n2w   = (const float*)d_in[8];
    const float* n2b   = (const float*)d_in[9];
    const float* fc1w  = (const float*)d_in[10];
    const float* fc1b  = (const float*)d_in[11];
    const float* fc2w  = (const float*)d_in[12];
    const float* fc2b  = (const float*)d_in[13];
    float* out = (float*)d_out;

    float *p_xw, *p_qkv, *p_att, *p_x2, *p_hn, *p_h3;
    cudaGetSymbolAddress((void**)&p_xw,  g_xw);
    cudaGetSymbolAddress((void**)&p_qkv, g_qkv);
    cudaGetSymbolAddress((void**)&p_att, g_att);
    cudaGetSymbolAddress((void**)&p_x2,  g_x2);
    cudaGetSymbolAddress((void**)&p_hn,  g_hn);
    cudaGetSymbolAddress((void**)&p_h3,  g_h3);

    cudaFuncSetAttribute(attn_kernel, cudaFuncAttributeMaxDynamicSharedMemorySize, ATTN_SMEM);

    // 1. LN1 + roll + window partition
    ln_kernel<<<NTOK/8, 256>>>(x, p_xw, n1w, n1b, 0);
    // 2. QKV GEMM
    gemm64<0><<<dim3(768/64, NTOK/64), 256>>>(p_xw, qkvw, qkvb, nullptr, p_qkv, NTOK, 768, 256);
    // 3. windowed attention (bias + shift mask + softmax + AV)
    attn_kernel<<<BW_*HEADS, 128, ATTN_SMEM>>>(rpe);
    // 4. proj GEMM + window reverse + roll back + residual
    gemm64<2><<<dim3(256/64, NTOK/64), 256>>>(p_att, projw, projb, x, p_x2, NTOK, 256, 256);
    // 5. LN2
    ln_kernel<<<NTOK/8, 256>>>(p_x2, p_hn, n2w, n2b, 1);
    // 6. fc1 GEMM + GELU
    gemm64<1><<<dim3(1024/64, NTOK/64), 256>>>(p_hn, fc1w, fc1b, nullptr, p_h3, NTOK, 1024, 256);
    // 7. fc2 GEMM + residual -> out
    gemm64<3><<<dim3(256/64, NTOK/64), 256>>>(p_h3, fc2w, fc2b, p_x2, out, NTOK, 256, 1024);
}

// round 3
// speedup vs baseline: 2.0523x; 2.0523x over previous
#include <cuda_runtime.h>
#include <cuda_bf16.h>
#include <math.h>
#include <stdint.h>

// ---------------- problem constants ----------------
#define DIM   256
#define HEADS 8
#define HD    32
#define B_    2
#define T_    8
#define H_    56
#define W_    56
#define WT    2
#define WH    7
#define WW    7
#define STs   1
#define SHs   3
#define SWs   3
#define NTOK  (B_*T_*H_*W_)   // 50176 = 392*128
#define BW_   512
#define N_    98
#define HID   1024

// ---------------- scratch (device globals) ----------
__device__ __nv_bfloat16 g_xw [NTOK*768];          // LN1 split-bf16 [hi,lo,hi]
__device__ float         g_qkv[(size_t)NTOK*768];
__device__ __nv_bfloat16 g_att[NTOK*768];          // attn out split-bf16
__device__ float         g_x2 [NTOK*256];          // residual-1
__device__ __nv_bfloat16 g_hn [NTOK*768];          // LN2 split-bf16
__device__ __nv_bfloat16 g_h3 [(size_t)NTOK*3072]; // fc1+gelu split-bf16
__device__ __nv_bfloat16 g_wqkv [768*768];
__device__ __nv_bfloat16 g_wproj[256*768];
__device__ __nv_bfloat16 g_wfc1 [1024*768];
__device__ __nv_bfloat16 g_wfc2 [256*3072];

// ---------------- PTX helpers ----------------------
__device__ __forceinline__ uint32_t smem_u32(const void* p) {
    uint32_t a;
    asm("{ .reg .u64 t; cvta.to.shared.u64 t, %1; cvt.u32.u64 %0, t; }" : "=r"(a) : "l"(p));
    return a;
}
#define CP_ASYNC16(sm, gp) \
    asm volatile("cp.async.cg.shared.global [%0], [%1], 16;" :: "r"(sm), "l"(gp))
#define CP_COMMIT() asm volatile("cp.async.commit_group;" ::: "memory")
#define CP_WAIT0()  asm volatile("cp.async.wait_group 0;" ::: "memory")
#define CP_WAIT1()  asm volatile("cp.async.wait_group 1;" ::: "memory")

// ---------------- split-bf16 helpers ----------------
__device__ __forceinline__ uint32_t pack2(__nv_bfloat16 a, __nv_bfloat16 b) {
    return (uint32_t)__bfloat16_as_ushort(a) | ((uint32_t)__bfloat16_as_ushort(b) << 16);
}
// activation split form: seg0=hi, seg1=lo, seg2=hi (K = logical width)
__device__ __forceinline__ void split_store4(__nv_bfloat16* rowp, int col, int K,
                                             float a0, float a1, float a2, float a3) {
    __nv_bfloat16 b0 = __float2bfloat16_rn(a0), b1 = __float2bfloat16_rn(a1);
    __nv_bfloat16 b2 = __float2bfloat16_rn(a2), b3 = __float2bfloat16_rn(a3);
    float l0 = a0 - __bfloat162float(b0), l1 = a1 - __bfloat162float(b1);
    float l2 = a2 - __bfloat162float(b2), l3 = a3 - __bfloat162float(b3);
    uint2 hiu; hiu.x = pack2(b0, b1); hiu.y = pack2(b2, b3);
    uint2 lou; lou.x = pack2(__float2bfloat16_rn(l0), __float2bfloat16_rn(l1));
    lou.y = pack2(__float2bfloat16_rn(l2), __float2bfloat16_rn(l3));
    *(uint2*)(rowp + col)       = hiu;
    *(uint2*)(rowp + K + col)   = lou;
    *(uint2*)(rowp + 2*K + col) = hiu;
}

// ---------------- weight conversion: [hi, hi, lo] -------------------
__global__ void convert_w(const float* __restrict__ src, __nv_bfloat16* __restrict__ dst,
                          int Nn, int K) {
    int idx = blockIdx.x * 256 + threadIdx.x;
    if (idx >= Nn * K) return;
    int n = idx / K, k = idx % K;
    float v = src[idx];
    __nv_bfloat16 hi = __float2bfloat16_rn(v);
    float lo = v - __bfloat162float(hi);
    __nv_bfloat16* r = dst + (size_t)n * 3 * K;
    r[k]       = hi;
    r[K + k]   = hi;
    r[2*K + k] = __float2bfloat16_rn(lo);
}

// ---------------- LN kernel -> split-bf16 (mode 0: +roll+partition) --------
__global__ void ln_kernel(const float* __restrict__ src, __nv_bfloat16* __restrict__ dst,
                          const float* __restrict__ w, const float* __restrict__ b, int mode) {
    int warp = threadIdx.x >> 5, lane = threadIdx.x & 31;
    int row = blockIdx.x * 8 + warp;
    const float* sr = src + (size_t)row * DIM;
    float4 v0 = *(const float4*)(sr + lane * 4);
    float4 v1 = *(const float4*)(sr + 128 + lane * 4);
    float s  = v0.x + v0.y + v0.z + v0.w + v1.x + v1.y + v1.z + v1.w;
    float ss = v0.x*v0.x + v0.y*v0.y + v0.z*v0.z + v0.w*v0.w
             + v1.x*v1.x + v1.y*v1.y + v1.z*v1.z + v1.w*v1.w;
    #pragma unroll
    for (int o = 16; o > 0; o >>= 1) {
        s  += __shfl_xor_sync(0xffffffffu, s, o);
        ss += __shfl_xor_sync(0xffffffffu, ss, o);
    }
    float mean = s * (1.0f / 256.0f);
    float var  = ss * (1.0f / 256.0f) - mean * mean;
    float inv  = rsqrtf(var + 1e-5f);

    size_t drow = row;
    if (mode == 0) {
        int bb = row / (T_*H_*W_);
        int r2 = row % (T_*H_*W_);
        int t = r2 / (H_*W_);
        int r3 = r2 % (H_*W_);
        int h = r3 / W_, ww_ = r3 % W_;
        int t2 = t - STs; if (t2 < 0) t2 += T_;
        int h2 = h - SHs; if (h2 < 0) h2 += H_;
        int w2 = ww_ - SWs; if (w2 < 0) w2 += W_;
        int tw = t2 / WT, hw = h2 / WH, wwn = w2 / WW;
        int n = (t2 % WT) * 49 + (h2 % WH) * 7 + (w2 % WW);
        int bw = ((bb * 4 + tw) * 8 + hw) * 8 + wwn;
        drow = (size_t)bw * N_ + n;
    }
    __nv_bfloat16* dr = dst + drow * 768;
    int c0 = lane * 4, c1 = 128 + lane * 4;
    split_store4(dr, c0, 256,
        (v0.x - mean) * inv * w[c0+0] + b[c0+0], (v0.y - mean) * inv * w[c0+1] + b[c0+1],
        (v0.z - mean) * inv * w[c0+2] + b[c0+2], (v0.w - mean) * inv * w[c0+3] + b[c0+3]);
    split_store4(dr, c1, 256,
        (v1.x - mean) * inv * w[c1+0] + b[c1+0], (v1.y - mean) * inv * w[c1+1] + b[c1+1],
        (v1.z - mean) * inv * w[c1+2] + b[c1+2], (v1.w - mean) * inv * w[c1+3] + b[c1+3]);
}

// ---------------- mma.sync GEMM: C[M,Ncols] = A[M,K3]@W[Ncols,K3]^T --------
// block 128x128, 8 warps (2x4), warp tile 64x32, K-chunk 64, cp.async 2-stage.
// SMEM rows strided 144B (conflict-free ldmatrix).
// EPI 0: +bias -> fp32 (qkv)   EPI 1: +bias,GELU -> split-bf16 (fc1)
// EPI 2: +bias, reverse+roll remap, +resid -> fp32 (proj)
// EPI 3: +bias, +resid -> fp32 (fc2)
#define ABUF 18432          // 128 rows * 144B
#define BUFSZ (2*ABUF)      // A+B per stage
#define GEMM_SMEM (2*BUFSZ) // 73728

template<int EPI>
__global__ __launch_bounds__(256) void gemm_mma(
        const __nv_bfloat16* __restrict__ A, const __nv_bfloat16* __restrict__ Wm,
        const float* __restrict__ bias, const float* __restrict__ resid,
        float* __restrict__ outF, __nv_bfloat16* __restrict__ outB, int K3) {
    extern __shared__ __align__(16) char smraw[];
    int tid = threadIdx.x, lane = tid & 31, wid = tid >> 5;
    int brow = blockIdx.y * 128, bcol = blockIdx.x * 128;
    int wm = wid & 1, wn = wid >> 1;
    uint32_t sb = smem_u32(smraw);

    float acc[4][4][4] = {};
    const int NC = K3 >> 6;

    const char* Agc = (const char*)(A  + (size_t)brow * K3);
    const char* Bgc = (const char*)(Wm + (size_t)bcol * K3);
    size_t rowstride = (size_t)K3 * 2;

    // chunk loader: 2048 16B-pieces (A:1024, B:1024), 8 per thread
    auto loadChunk = [&](int c) {
        int buf = c & 1;
        uint32_t abase = sb + buf * BUFSZ;
        uint32_t bbase = abase + ABUF;
        const char* Ag = Agc + (size_t)c * 128;  // c*64 elems * 2B
        const char* Bg = Bgc + (size_t)c * 128;
        #pragma unroll
        for (int j = 0; j < 4; j++) {
            int x = tid + j * 256;            // 0..1023
            int row = x >> 3, kc = x & 7;
            CP_ASYNC16(abase + row * 144 + kc * 16, Ag + (size_t)row * rowstride + kc * 16);
            CP_ASYNC16(bbase + row * 144 + kc * 16, Bg + (size_t)row * rowstride + kc * 16);
        }
        CP_COMMIT();
    };

    loadChunk(0);
    for (int c = 0; c < NC; c++) {
        if (c + 1 < NC) { loadChunk(c + 1); CP_WAIT1(); } else { CP_WAIT0(); }
        __syncthreads();
        int buf = c & 1;
        uint32_t abase = sb + buf * BUFSZ;
        uint32_t bbase = abase + ABUF;
        #pragma unroll
        for (int kh = 0; kh < 4; kh++) {
            uint32_t afr[4][4];
            #pragma unroll
            for (int mt = 0; mt < 4; mt++) {
                int row = wm * 64 + mt * 16 + ((lane >> 3) & 1) * 8 + (lane & 7);
                uint32_t addr = abase + row * 144 + kh * 32 + (lane >> 4) * 16;
                asm volatile("ldmatrix.sync.aligned.m8n8.x4.shared.b16 {%0,%1,%2,%3}, [%4];"
                    : "=r"(afr[mt][0]), "=r"(afr[mt][1]), "=r"(afr[mt][2]), "=r"(afr[mt][3])
                    : "r"(addr));
            }
            uint32_t bfr[4][2];
            #pragma unroll
            for (int np = 0; np < 2; np++) {
                int nrow = wn * 32 + np * 16 + (lane >> 4) * 8 + (lane & 7);
                uint32_t addr = bbase + nrow * 144 + kh * 32 + ((lane >> 3) & 1) * 16;
                uint32_t r0, r1, r2, r3;
                asm volatile("ldmatrix.sync.aligned.m8n8.x4.shared.b16 {%0,%1,%2,%3}, [%4];"
                    : "=r"(r0), "=r"(r1), "=r"(r2), "=r"(r3) : "r"(addr));
                bfr[np*2][0] = r0; bfr[np*2][1] = r1;
                bfr[np*2+1][0] = r2; bfr[np*2+1][1] = r3;
            }
            #pragma unroll
            for (int mt = 0; mt < 4; mt++)
                #pragma unroll
                for (int nt = 0; nt < 4; nt++)
                    asm volatile(
                        "mma.sync.aligned.m16n8k16.row.col.f32.bf16.bf16.f32 "
                        "{%0,%1,%2,%3}, {%4,%5,%6,%7}, {%8,%9}, {%0,%1,%2,%3};"
                        : "+f"(acc[mt][nt][0]), "+f"(acc[mt][nt][1]),
                          "+f"(acc[mt][nt][2]), "+f"(acc[mt][nt][3])
                        : "r"(afr[mt][0]), "r"(afr[mt][1]), "r"(afr[mt][2]), "r"(afr[mt][3]),
                          "r"(bfr[nt][0]), "r"(bfr[nt][1]));
        }
        __syncthreads();
    }

    // ---- epilogue: accs -> SMEM (stride 132 f32) -> coalesced stores ----
    float* Cs = (float*)smraw;
    #pragma unroll
    for (int mt = 0; mt < 4; mt++)
        #pragma unroll
        for (int nt = 0; nt < 4; nt++) {
            int r0 = wm * 64 + mt * 16 + (lane >> 2);
            int cc = wn * 32 + nt * 8 + (lane & 3) * 2;
            Cs[r0 * 132 + cc]       = acc[mt][nt][0];
            Cs[r0 * 132 + cc + 1]   = acc[mt][nt][1];
            Cs[(r0+8) * 132 + cc]   = acc[mt][nt][2];
            Cs[(r0+8) * 132 + cc+1] = acc[mt][nt][3];
        }
    __syncthreads();

    float4 bs = *(const float4*)(bias + bcol + lane * 4);
    for (int r = wid; r < 128; r += 8) {
        float4 v = *(const float4*)&Cs[r * 132 + lane * 4];
        v.x += bs.x; v.y += bs.y; v.z += bs.z; v.w += bs.w;
        int grow = brow + r;
        int col = bcol + lane * 4;
        if (EPI == 0) {
            *(float4*)(outF + (size_t)grow * 768 + col) = v;
        } else if (EPI == 1) {
            float g0 = 0.5f * v.x * (1.0f + erff(v.x * 0.70710678118654752f));
            float g1 = 0.5f * v.y * (1.0f + erff(v.y * 0.70710678118654752f));
            float g2 = 0.5f * v.z * (1.0f + erff(v.z * 0.70710678118654752f));
            float g3 = 0.5f * v.w * (1.0f + erff(v.w * 0.70710678118654752f));
            split_store4(outB + (size_t)grow * 3072, col, 1024, g0, g1, g2, g3);
        } else if (EPI == 2) {
            int bw = grow / N_, n = grow % N_;
            int bb = bw >> 8, wrem = bw & 255;
            int tw = wrem >> 6, hw = (wrem >> 3) & 7, wwn = wrem & 7;
            int nt = n / 49, nr = n % 49;
            int t2 = tw*WT + nt, h2 = hw*WH + nr/7, w2 = wwn*WW + nr%7;
            int t = t2 + STs; if (t >= T_) t -= T_;
            int h = h2 + SHs; if (h >= H_) h -= H_;
            int ww_ = w2 + SWs; if (ww_ >= W_) ww_ -= W_;
            size_t orow = ((size_t)((bb*T_ + t)*H_ + h))*W_ + ww_;
            float4 rr = *(const float4*)(resid + orow * 256 + col);
            v.x += rr.x; v.y += rr.y; v.z += rr.z; v.w += rr.w;
            *(float4*)(outF + orow * 256 + col) = v;
        } else {
            float4 rr = *(const float4*)(resid + (size_t)grow * 256 + col);
            v.x += rr.x; v.y += rr.y; v.z += rr.z; v.w += rr.w;
            *(float4*)(outF + (size_t)grow * 256 + col) = v;
        }
    }
}

// ---------------- attention: one block per (window, head) ------------------
__global__ void attn_kernel(const float* __restrict__ rpe) {
    extern __shared__ float sm[];
    float* qs = sm;
    float* ks = sm + 98*32;
    float* vs = sm + 2*98*32;
    float* ps = sm + 3*98*32;        // 98*99
    int*   tc = (int*)(ps + 98*99);

    int bid  = blockIdx.x;
    int head = bid & 7;
    int bw   = bid >> 3;
    int wrem = bw & 255;
    int tw = wrem >> 6, hw = (wrem >> 3) & 7, wwn = wrem & 7;
    int tid = threadIdx.x;

    const float* qbase = g_qkv + ((size_t)bw * N_) * 768 + head * HD;
    for (int i = tid; i < N_*HD; i += 128) {
        int m = i >> 5, d = i & 31;
        size_t o = (size_t)m * 768 + d;
        qs[i] = qbase[o];
        ks[i] = qbase[o + 256];
        vs[i] = qbase[o + 512];
    }
    if (tid < N_) {
        int t = tid / 49, rem = tid % 49, h = rem / 7, w = rem % 7;
        int gt = tw*WT + t, gh = hw*WH + h, gw = wwn*WW + w;
        int rt = (gt < T_-WT) ? 0 : ((gt < T_-STs) ? 1 : 2);
        int rh = (gh < H_-WH) ? 0 : ((gh < H_-SHs) ? 1 : 2);
        int rw = (gw < W_-WW) ? 0 : ((gw < W_-SWs) ? 1 : 2);
        tc[tid] = t | (h << 4) | (w << 8) | ((rt*9 + rh*3 + rw) << 12);
    }
    __syncthreads();

    if (tid < N_) {
        int r = tid;
        int pc = tc[r];
        int tr = pc & 15, hr = (pc >> 4) & 15, wr = (pc >> 8) & 15, regr = pc >> 12;
        float qreg[HD];
        const float* qrow = qs + r*HD;
        #pragma unroll
        for (int d = 0; d < HD; d++) qreg[d] = qrow[d] * 0.17677669529663687f;

        float* prow = ps + r*99;
        float mx = -1e30f;
        for (int m = 0; m < N_; m++) {
            const float* krow = ks + m*HD;
            float s = 0.f;
            #pragma unroll
            for (int d = 0; d < HD; d++) s = fmaf(qreg[d], krow[d], s);
            int pm = tc[m];
            int idx = (tr - (pm & 15) + (WT-1)) * ((2*WH-1)*(2*WW-1))
                    + (hr - ((pm >> 4) & 15) + (WH-1)) * (2*WW-1)
                    + (wr - ((pm >> 8) & 15) + (WW-1));
            s += __ldg(&rpe[idx * HEADS + head]);
            if (regr != (pm >> 12)) s -= 100.0f;
            prow[m] = s;
            mx = fmaxf(mx, s);
        }
        float sum = 0.f;
        for (int m = 0; m < N_; m++) {
            float e = __expf(prow[m] - mx);
            prow[m] = e;
            sum += e;
        }
        float invs = 1.0f / sum;

        __nv_bfloat16* orow = g_att + ((size_t)(bw*N_ + r)) * 768;
        #pragma unroll
        for (int d0 = 0; d0 < HD; d0 += 8) {
            float acc[8] = {};
            for (int m = 0; m < N_; m++) {
                float p = prow[m];
                const float* vr = vs + m*HD + d0;
                #pragma unroll
                for (int j = 0; j < 8; j++) acc[j] = fmaf(p, vr[j], acc[j]);
            }
            int col = head*HD + d0;
            split_store4(orow, col,     256, acc[0]*invs, acc[1]*invs, acc[2]*invs, acc[3]*invs);
            split_store4(orow, col + 4, 256, acc[4]*invs, acc[5]*invs, acc[6]*invs, acc[7]*invs);
        }
    }
}
#define ATTN_SMEM ((3*98*32 + 98*99) * 4 + 98 * 4)

// ---------------- host launcher ---------------------------------------------
extern "C" void kernel_launch(void* const* d_in, const int* in_sizes, int n_in,
                              void* d_out, int out_size) {
    const float* x     = (const float*)d_in[0];
    const float* n1w   = (const float*)d_in[1];
    const float* n1b   = (const float*)d_in[2];
    const float* qkvw  = (const float*)d_in[3];
    const float* qkvb  = (const float*)d_in[4];
    const float* projw = (const float*)d_in[5];
    const float* projb = (const float*)d_in[6];
    const float* rpe   = (const float*)d_in[7];
    const float* n2w   = (const float*)d_in[8];
    const float* n2b   = (const float*)d_in[9];
    const float* fc1w  = (const float*)d_in[10];
    const float* fc1b  = (const float*)d_in[11];
    const float* fc2w  = (const float*)d_in[12];
    const float* fc2b  = (const float*)d_in[13];
    float* out = (float*)d_out;

    __nv_bfloat16 *p_xw, *p_att, *p_hn, *p_h3, *p_wqkv, *p_wproj, *p_wfc1, *p_wfc2;
    float *p_qkv, *p_x2;
    cudaGetSymbolAddress((void**)&p_xw,  g_xw);
    cudaGetSymbolAddress((void**)&p_qkv, g_qkv);
    cudaGetSymbolAddress((void**)&p_att, g_att);
    cudaGetSymbolAddress((void**)&p_x2,  g_x2);
    cudaGetSymbolAddress((void**)&p_hn,  g_hn);
    cudaGetSymbolAddress((void**)&p_h3,  g_h3);
    cudaGetSymbolAddress((void**)&p_wqkv,  g_wqkv);
    cudaGetSymbolAddress((void**)&p_wproj, g_wproj);
    cudaGetSymbolAddress((void**)&p_wfc1,  g_wfc1);
    cudaGetSymbolAddress((void**)&p_wfc2,  g_wfc2);

    cudaFuncSetAttribute(attn_kernel, cudaFuncAttributeMaxDynamicSharedMemorySize, ATTN_SMEM);
    cudaFuncSetAttribute(gemm_mma<0>, cudaFuncAttributeMaxDynamicSharedMemorySize, GEMM_SMEM);
    cudaFuncSetAttribute(gemm_mma<1>, cudaFuncAttributeMaxDynamicSharedMemorySize, GEMM_SMEM);
    cudaFuncSetAttribute(gemm_mma<2>, cudaFuncAttributeMaxDynamicSharedMemorySize, GEMM_SMEM);
    cudaFuncSetAttribute(gemm_mma<3>, cudaFuncAttributeMaxDynamicSharedMemorySize, GEMM_SMEM);

    // weight conversions (split-bf16 [hi, hi, lo])
    convert_w<<<(768*256 + 255)/256, 256>>>(qkvw,  p_wqkv, 768, 256);
    convert_w<<<(256*256 + 255)/256, 256>>>(projw, p_wproj, 256, 256);
    convert_w<<<(1024*256 + 255)/256, 256>>>(fc1w, p_wfc1, 1024, 256);
    convert_w<<<(256*1024 + 255)/256, 256>>>(fc2w, p_wfc2, 256, 1024);

    // 1. LN1 + roll + window partition -> split-bf16
    ln_kernel<<<NTOK/8, 256>>>(x, p_xw, n1w, n1b, 0);
    // 2. QKV GEMM
    gemm_mma<0><<<dim3(6, 392), 256, GEMM_SMEM>>>(p_xw, p_wqkv, qkvb, nullptr, p_qkv, nullptr, 768);
    // 3. windowed attention
    attn_kernel<<<BW_*HEADS, 128, ATTN_SMEM>>>(rpe);
    // 4. proj GEMM + reverse/roll + residual
    gemm_mma<2><<<dim3(2, 392), 256, GEMM_SMEM>>>(p_att, p_wproj, projb, x, p_x2, nullptr, 768);
    // 5. LN2 -> split-bf16
    ln_kernel<<<NTOK/8, 256>>>(p_x2, p_hn, n2w, n2b, 1);
    // 6. fc1 GEMM + GELU -> split-bf16
    gemm_mma<1><<<dim3(8, 392), 256, GEMM_SMEM>>>(p_hn, p_wfc1, fc1b, nullptr, nullptr, p_h3, 768);
    // 7. fc2 GEMM + residual -> out
    gemm_mma<3><<<dim3(2, 392), 256, GEMM_SMEM>>>(p_h3, p_wfc2, fc2b, p_x2, out, nullptr, 3072);
}

// round 4
// speedup vs baseline: 3.3008x; 1.6083x over previous
#include <cuda_runtime.h>
#include <cuda_bf16.h>
#include <math.h>
#include <stdint.h>

// ---------------- problem constants ----------------
#define DIM   256
#define HEADS 8
#define HD    32
#define B_    2
#define T_    8
#define H_    56
#define W_    56
#define WT    2
#define WH    7
#define WW    7
#define STs   1
#define SHs   3
#define SWs   3
#define NTOK  (B_*T_*H_*W_)   // 50176 = 392*128
#define BW_   512
#define N_    98
#define HID   1024

// ---------------- scratch (device globals) ----------
__device__ __nv_bfloat16 g_xw [NTOK*768];          // LN1 split-bf16 [hi,lo,hi]
__device__ float         g_qkv[(size_t)NTOK*768];
__device__ __nv_bfloat16 g_att[NTOK*768];          // attn out split-bf16
__device__ float         g_x2 [NTOK*256];          // residual-1
__device__ __nv_bfloat16 g_hn [NTOK*256];          // LN2 plain bf16
__device__ __nv_bfloat16 g_h3 [(size_t)NTOK*1024]; // fc1+gelu plain bf16
__device__ __nv_bfloat16 g_wqkv [768*768];         // 3-seg
__device__ __nv_bfloat16 g_wproj[256*768];         // 3-seg
__device__ __nv_bfloat16 g_wfc1 [1024*256];        // plain
__device__ __nv_bfloat16 g_wfc2 [256*1024];        // plain

// ---------------- PTX helpers ----------------------
__device__ __forceinline__ uint32_t smem_u32(const void* p) {
    uint32_t a;
    asm("{ .reg .u64 t; cvta.to.shared.u64 t, %1; cvt.u32.u64 %0, t; }" : "=r"(a) : "l"(p));
    return a;
}
#define CP_ASYNC16(sm, gp) \
    asm volatile("cp.async.cg.shared.global [%0], [%1], 16;" :: "r"(sm), "l"(gp))
#define CP_COMMIT() asm volatile("cp.async.commit_group;" ::: "memory")
#define CP_WAIT0()  asm volatile("cp.async.wait_group 0;" ::: "memory")
#define CP_WAIT1()  asm volatile("cp.async.wait_group 1;" ::: "memory")

// ---------------- split-bf16 helpers ----------------
__device__ __forceinline__ uint32_t pack2(__nv_bfloat16 a, __nv_bfloat16 b) {
    return (uint32_t)__bfloat16_as_ushort(a) | ((uint32_t)__bfloat16_as_ushort(b) << 16);
}
__device__ __forceinline__ void split_store4(__nv_bfloat16* rowp, int col, int K,
                                             float a0, float a1, float a2, float a3) {
    __nv_bfloat16 b0 = __float2bfloat16_rn(a0), b1 = __float2bfloat16_rn(a1);
    __nv_bfloat16 b2 = __float2bfloat16_rn(a2), b3 = __float2bfloat16_rn(a3);
    float l0 = a0 - __bfloat162float(b0), l1 = a1 - __bfloat162float(b1);
    float l2 = a2 - __bfloat162float(b2), l3 = a3 - __bfloat162float(b3);
    uint2 hiu; hiu.x = pack2(b0, b1); hiu.y = pack2(b2, b3);
    uint2 lou; lou.x = pack2(__float2bfloat16_rn(l0), __float2bfloat16_rn(l1));
    lou.y = pack2(__float2bfloat16_rn(l2), __float2bfloat16_rn(l3));
    *(uint2*)(rowp + col)       = hiu;
    *(uint2*)(rowp + K + col)   = lou;
    *(uint2*)(rowp + 2*K + col) = hiu;
}
__device__ __forceinline__ void plain_store4(__nv_bfloat16* rowp, int col,
                                             float a0, float a1, float a2, float a3) {
    uint2 u;
    u.x = pack2(__float2bfloat16_rn(a0), __float2bfloat16_rn(a1));
    u.y = pack2(__float2bfloat16_rn(a2), __float2bfloat16_rn(a3));
    *(uint2*)(rowp + col) = u;
}

// ---------------- weight conversion -------------------
__global__ void convert_w(const float* __restrict__ src, __nv_bfloat16* __restrict__ dst,
                          int Nn, int K, int segs) {
    int idx = blockIdx.x * 256 + threadIdx.x;
    if (idx >= Nn * K) return;
    int n = idx / K, k = idx % K;
    float v = src[idx];
    __nv_bfloat16 hi = __float2bfloat16_rn(v);
    if (segs == 3) {
        float lo = v - __bfloat162float(hi);
        __nv_bfloat16* r = dst + (size_t)n * 3 * K;
        r[k]       = hi;
        r[K + k]   = hi;
        r[2*K + k] = __float2bfloat16_rn(lo);
    } else {
        dst[(size_t)n * K + k] = hi;
    }
}

// ---------------- LN kernel (mode 0: +roll+partition -> 3-seg; mode 1: plain bf16)
__global__ void ln_kernel(const float* __restrict__ src, __nv_bfloat16* __restrict__ dst,
                          const float* __restrict__ w, const float* __restrict__ b, int mode) {
    int warp = threadIdx.x >> 5, lane = threadIdx.x & 31;
    int row = blockIdx.x * 8 + warp;
    const float* sr = src + (size_t)row * DIM;
    float4 v0 = *(const float4*)(sr + lane * 4);
    float4 v1 = *(const float4*)(sr + 128 + lane * 4);
    float s  = v0.x + v0.y + v0.z + v0.w + v1.x + v1.y + v1.z + v1.w;
    float ss = v0.x*v0.x + v0.y*v0.y + v0.z*v0.z + v0.w*v0.w
             + v1.x*v1.x + v1.y*v1.y + v1.z*v1.z + v1.w*v1.w;
    #pragma unroll
    for (int o = 16; o > 0; o >>= 1) {
        s  += __shfl_xor_sync(0xffffffffu, s, o);
        ss += __shfl_xor_sync(0xffffffffu, ss, o);
    }
    float mean = s * (1.0f / 256.0f);
    float var  = ss * (1.0f / 256.0f) - mean * mean;
    float inv  = rsqrtf(var + 1e-5f);
    int c0 = lane * 4, c1 = 128 + lane * 4;
    float o00 = (v0.x - mean) * inv * w[c0+0] + b[c0+0];
    float o01 = (v0.y - mean) * inv * w[c0+1] + b[c0+1];
    float o02 = (v0.z - mean) * inv * w[c0+2] + b[c0+2];
    float o03 = (v0.w - mean) * inv * w[c0+3] + b[c0+3];
    float o10 = (v1.x - mean) * inv * w[c1+0] + b[c1+0];
    float o11 = (v1.y - mean) * inv * w[c1+1] + b[c1+1];
    float o12 = (v1.z - mean) * inv * w[c1+2] + b[c1+2];
    float o13 = (v1.w - mean) * inv * w[c1+3] + b[c1+3];

    if (mode == 0) {
        int bb = row / (T_*H_*W_);
        int r2 = row % (T_*H_*W_);
        int t = r2 / (H_*W_);
        int r3 = r2 % (H_*W_);
        int h = r3 / W_, ww_ = r3 % W_;
        int t2 = t - STs; if (t2 < 0) t2 += T_;
        int h2 = h - SHs; if (h2 < 0) h2 += H_;
        int w2 = ww_ - SWs; if (w2 < 0) w2 += W_;
        int tw = t2 / WT, hw = h2 / WH, wwn = w2 / WW;
        int n = (t2 % WT) * 49 + (h2 % WH) * 7 + (w2 % WW);
        int bw = ((bb * 4 + tw) * 8 + hw) * 8 + wwn;
        __nv_bfloat16* dr = dst + ((size_t)bw * N_ + n) * 768;
        split_store4(dr, c0, 256, o00, o01, o02, o03);
        split_store4(dr, c1, 256, o10, o11, o12, o13);
    } else {
        __nv_bfloat16* dr = dst + (size_t)row * 256;
        plain_store4(dr, c0, o00, o01, o02, o03);
        plain_store4(dr, c1, o10, o11, o12, o13);
    }
}

// ---------------- mma.sync GEMM: C[M,Ncols] = A[M,K3]@W[Ncols,K3]^T --------
// block 128x128, 8 warps (2x4), warp tile 64x32, K-chunk 64, cp.async 2-stage.
// EPI 0: +bias -> fp32 (qkv)   EPI 1: +bias,GELU -> plain bf16 K=1024 (fc1)
// EPI 2: +bias, reverse+roll remap, +resid -> fp32 (proj)
// EPI 3: +bias, +resid -> fp32 (fc2)
#define ABUF 18432          // 128 rows * 144B
#define BUFSZ (2*ABUF)      // A+B per stage
#define GEMM_SMEM (2*BUFSZ) // 73728

template<int EPI>
__global__ __launch_bounds__(256) void gemm_mma(
        const __nv_bfloat16* __restrict__ A, const __nv_bfloat16* __restrict__ Wm,
        const float* __restrict__ bias, const float* __restrict__ resid,
        float* __restrict__ outF, __nv_bfloat16* __restrict__ outB, int K3) {
    extern __shared__ __align__(16) char smraw[];
    int tid = threadIdx.x, lane = tid & 31, wid = tid >> 5;
    int brow = blockIdx.y * 128, bcol = blockIdx.x * 128;
    int wm = wid & 1, wn = wid >> 1;
    uint32_t sb = smem_u32(smraw);

    float acc[4][4][4] = {};
    const int NC = K3 >> 6;

    const char* Agc = (const char*)(A  + (size_t)brow * K3);
    const char* Bgc = (const char*)(Wm + (size_t)bcol * K3);
    size_t rowstride = (size_t)K3 * 2;

    auto loadChunk = [&](int c) {
        int buf = c & 1;
        uint32_t abase = sb + buf * BUFSZ;
        uint32_t bbase = abase + ABUF;
        const char* Ag = Agc + (size_t)c * 128;
        const char* Bg = Bgc + (size_t)c * 128;
        #pragma unroll
        for (int j = 0; j < 4; j++) {
            int x = tid + j * 256;
            int row = x >> 3, kc = x & 7;
            CP_ASYNC16(abase + row * 144 + kc * 16, Ag + (size_t)row * rowstride + kc * 16);
            CP_ASYNC16(bbase + row * 144 + kc * 16, Bg + (size_t)row * rowstride + kc * 16);
        }
        CP_COMMIT();
    };

    loadChunk(0);
    for (int c = 0; c < NC; c++) {
        if (c + 1 < NC) { loadChunk(c + 1); CP_WAIT1(); } else { CP_WAIT0(); }
        __syncthreads();
        int buf = c & 1;
        uint32_t abase = sb + buf * BUFSZ;
        uint32_t bbase = abase + ABUF;
        #pragma unroll
        for (int kh = 0; kh < 4; kh++) {
            uint32_t afr[4][4];
            #pragma unroll
            for (int mt = 0; mt < 4; mt++) {
                int row = wm * 64 + mt * 16 + ((lane >> 3) & 1) * 8 + (lane & 7);
                uint32_t addr = abase + row * 144 + kh * 32 + (lane >> 4) * 16;
                asm volatile("ldmatrix.sync.aligned.m8n8.x4.shared.b16 {%0,%1,%2,%3}, [%4];"
                    : "=r"(afr[mt][0]), "=r"(afr[mt][1]), "=r"(afr[mt][2]), "=r"(afr[mt][3])
                    : "r"(addr));
            }
            uint32_t bfr[4][2];
            #pragma unroll
            for (int np = 0; np < 2; np++) {
                int nrow = wn * 32 + np * 16 + (lane >> 4) * 8 + (lane & 7);
                uint32_t addr = bbase + nrow * 144 + kh * 32 + ((lane >> 3) & 1) * 16;
                uint32_t r0, r1, r2, r3;
                asm volatile("ldmatrix.sync.aligned.m8n8.x4.shared.b16 {%0,%1,%2,%3}, [%4];"
                    : "=r"(r0), "=r"(r1), "=r"(r2), "=r"(r3) : "r"(addr));
                bfr[np*2][0] = r0; bfr[np*2][1] = r1;
                bfr[np*2+1][0] = r2; bfr[np*2+1][1] = r3;
            }
            #pragma unroll
            for (int mt = 0; mt < 4; mt++)
                #pragma unroll
                for (int nt = 0; nt < 4; nt++)
                    asm volatile(
                        "mma.sync.aligned.m16n8k16.row.col.f32.bf16.bf16.f32 "
                        "{%0,%1,%2,%3}, {%4,%5,%6,%7}, {%8,%9}, {%0,%1,%2,%3};"
                        : "+f"(acc[mt][nt][0]), "+f"(acc[mt][nt][1]),
                          "+f"(acc[mt][nt][2]), "+f"(acc[mt][nt][3])
                        : "r"(afr[mt][0]), "r"(afr[mt][1]), "r"(afr[mt][2]), "r"(afr[mt][3]),
                          "r"(bfr[nt][0]), "r"(bfr[nt][1]));
        }
        __syncthreads();
    }

    // ---- epilogue: accs -> SMEM (stride 132 f32) -> coalesced stores ----
    float* Cs = (float*)smraw;
    #pragma unroll
    for (int mt = 0; mt < 4; mt++)
        #pragma unroll
        for (int nt = 0; nt < 4; nt++) {
            int r0 = wm * 64 + mt * 16 + (lane >> 2);
            int cc = wn * 32 + nt * 8 + (lane & 3) * 2;
            Cs[r0 * 132 + cc]       = acc[mt][nt][0];
            Cs[r0 * 132 + cc + 1]   = acc[mt][nt][1];
            Cs[(r0+8) * 132 + cc]   = acc[mt][nt][2];
            Cs[(r0+8) * 132 + cc+1] = acc[mt][nt][3];
        }
    __syncthreads();

    float4 bs = *(const float4*)(bias + bcol + lane * 4);
    for (int r = wid; r < 128; r += 8) {
        float4 v = *(const float4*)&Cs[r * 132 + lane * 4];
        v.x += bs.x; v.y += bs.y; v.z += bs.z; v.w += bs.w;
        int grow = brow + r;
        int col = bcol + lane * 4;
        if (EPI == 0) {
            *(float4*)(outF + (size_t)grow * 768 + col) = v;
        } else if (EPI == 1) {
            float g0 = 0.5f * v.x * (1.0f + erff(v.x * 0.70710678118654752f));
            float g1 = 0.5f * v.y * (1.0f + erff(v.y * 0.70710678118654752f));
            float g2 = 0.5f * v.z * (1.0f + erff(v.z * 0.70710678118654752f));
            float g3 = 0.5f * v.w * (1.0f + erff(v.w * 0.70710678118654752f));
            plain_store4(outB + (size_t)grow * 1024, col, g0, g1, g2, g3);
        } else if (EPI == 2) {
            int bw = grow / N_, n = grow % N_;
            int bb = bw >> 8, wrem = bw & 255;
            int tw = wrem >> 6, hw = (wrem >> 3) & 7, wwn = wrem & 7;
            int nt = n / 49, nr = n % 49;
            int t2 = tw*WT + nt, h2 = hw*WH + nr/7, w2 = wwn*WW + nr%7;
            int t = t2 + STs; if (t >= T_) t -= T_;
            int h = h2 + SHs; if (h >= H_) h -= H_;
            int ww_ = w2 + SWs; if (ww_ >= W_) ww_ -= W_;
            size_t orow = ((size_t)((bb*T_ + t)*H_ + h))*W_ + ww_;
            float4 rr = *(const float4*)(resid + orow * 256 + col);
            v.x += rr.x; v.y += rr.y; v.z += rr.z; v.w += rr.w;
            *(float4*)(outF + orow * 256 + col) = v;
        } else {
            float4 rr = *(const float4*)(resid + (size_t)grow * 256 + col);
            v.x += rr.x; v.y += rr.y; v.z += rr.z; v.w += rr.w;
            *(float4*)(outF + (size_t)grow * 256 + col) = v;
        }
    }
}

// ---------------- attention: one block per (window, head) ------------------
// q in registers, k/v in smem (fp32), scores in smem stride 99.
__global__ __launch_bounds__(128) void attn_kernel(const float* __restrict__ rpe) {
    extern __shared__ float sm[];
    float* ks = sm;                  // 98*32
    float* vs = sm + 98*32;          // 98*32
    float* ps = sm + 2*98*32;        // 98*99
    int*   tc = (int*)(ps + 98*99);  // 98

    int bid  = blockIdx.x;
    int head = bid & 7;
    int bw   = bid >> 3;
    int wrem = bw & 255;
    int tw = wrem >> 6, hw = (wrem >> 3) & 7, wwn = wrem & 7;
    int tid = threadIdx.x;

    const float* qbase = g_qkv + ((size_t)bw * N_) * 768 + head * HD;
    for (int i = tid; i < N_*HD; i += 128) {
        int m = i >> 5, d = i & 31;
        size_t o = (size_t)m * 768 + d;
        ks[i] = qbase[o + 256];
        vs[i] = qbase[o + 512];
    }
    if (tid < N_) {
        int t = tid / 49, rem = tid % 49, h = rem / 7, w = rem % 7;
        int gt = tw*WT + t, gh = hw*WH + h, gw = wwn*WW + w;
        int rt = (gt < T_-WT) ? 0 : ((gt < T_-STs) ? 1 : 2);
        int rh = (gh < H_-WH) ? 0 : ((gh < H_-SHs) ? 1 : 2);
        int rw = (gw < W_-WW) ? 0 : ((gw < W_-SWs) ? 1 : 2);
        tc[tid] = t | (h << 4) | (w << 8) | ((rt*9 + rh*3 + rw) << 12);
    }
    __syncthreads();

    if (tid < N_) {
        int r = tid;
        int pc = tc[r];
        int tr = pc & 15, hr = (pc >> 4) & 15, wr = (pc >> 8) & 15, regr = pc >> 12;
        float4 q4[8];
        const float4* qg = (const float4*)(qbase + (size_t)r * 768);
        #pragma unroll
        for (int i = 0; i < 8; i++) {
            q4[i] = qg[i];
            q4[i].x *= 0.17677669529663687f; q4[i].y *= 0.17677669529663687f;
            q4[i].z *= 0.17677669529663687f; q4[i].w *= 0.17677669529663687f;
        }

        float* prow = ps + r*99;
        float mx = -1e30f;
        for (int m = 0; m < N_; m++) {
            const float4* k4 = (const float4*)(ks + m*HD);
            float s0 = 0.f, s1 = 0.f, s2 = 0.f, s3 = 0.f;
            #pragma unroll
            for (int i = 0; i < 8; i++) {
                float4 kk = k4[i];
                s0 = fmaf(q4[i].x, kk.x, s0);
                s1 = fmaf(q4[i].y, kk.y, s1);
                s2 = fmaf(q4[i].z, kk.z, s2);
                s3 = fmaf(q4[i].w, kk.w, s3);
            }
            float s = (s0 + s1) + (s2 + s3);
            int pm = tc[m];
            int idx = (tr - (pm & 15) + (WT-1)) * ((2*WH-1)*(2*WW-1))
                    + (hr - ((pm >> 4) & 15) + (WH-1)) * (2*WW-1)
                    + (wr - ((pm >> 8) & 15) + (WW-1));
            s += __ldg(&rpe[idx * HEADS + head]);
            if (regr != (pm >> 12)) s -= 100.0f;
            prow[m] = s;
            mx = fmaxf(mx, s);
        }
        float sum = 0.f;
        for (int m = 0; m < N_; m++) {
            float e = __expf(prow[m] - mx);
            prow[m] = e;
            sum += e;
        }
        float invs = 1.0f / sum;

        float4 acc[8];
        #pragma unroll
        for (int i = 0; i < 8; i++) acc[i] = make_float4(0.f, 0.f, 0.f, 0.f);
        for (int m = 0; m < N_; m++) {
            float p = prow[m];
            const float4* v4 = (const float4*)(vs + m*HD);
            #pragma unroll
            for (int i = 0; i < 8; i++) {
                float4 vv = v4[i];
                acc[i].x = fmaf(p, vv.x, acc[i].x);
                acc[i].y = fmaf(p, vv.y, acc[i].y);
                acc[i].z = fmaf(p, vv.z, acc[i].z);
                acc[i].w = fmaf(p, vv.w, acc[i].w);
            }
        }
        __nv_bfloat16* orow = g_att + ((size_t)(bw*N_ + r)) * 768;
        #pragma unroll
        for (int i = 0; i < 8; i++) {
            split_store4(orow, head*HD + i*4, 256,
                acc[i].x*invs, acc[i].y*invs, acc[i].z*invs, acc[i].w*invs);
        }
    }
}
#define ATTN_SMEM ((2*98*32 + 98*99) * 4 + 98 * 4)

// ---------------- host launcher ---------------------------------------------
extern "C" void kernel_launch(void* const* d_in, const int* in_sizes, int n_in,
                              void* d_out, int out_size) {
    const float* x     = (const float*)d_in[0];
    const float* n1w   = (const float*)d_in[1];
    const float* n1b   = (const float*)d_in[2];
    const float* qkvw  = (const float*)d_in[3];
    const float* qkvb  = (const float*)d_in[4];
    const float* projw = (const float*)d_in[5];
    const float* projb = (const float*)d_in[6];
    const float* rpe   = (const float*)d_in[7];
    const float* n2w   = (const float*)d_in[8];
    const float* n2b   = (const float*)d_in[9];
    const float* fc1w  = (const float*)d_in[10];
    const float* fc1b  = (const float*)d_in[11];
    const float* fc2w  = (const float*)d_in[12];
    const float* fc2b  = (const float*)d_in[13];
    float* out = (float*)d_out;

    __nv_bfloat16 *p_xw, *p_att, *p_hn, *p_h3, *p_wqkv, *p_wproj, *p_wfc1, *p_wfc2;
    float *p_qkv, *p_x2;
    cudaGetSymbolAddress((void**)&p_xw,  g_xw);
    cudaGetSymbolAddress((void**)&p_qkv, g_qkv);
    cudaGetSymbolAddress((void**)&p_att, g_att);
    cudaGetSymbolAddress((void**)&p_x2,  g_x2);
    cudaGetSymbolAddress((void**)&p_hn,  g_hn);
    cudaGetSymbolAddress((void**)&p_h3,  g_h3);
    cudaGetSymbolAddress((void**)&p_wqkv,  g_wqkv);
    cudaGetSymbolAddress((void**)&p_wproj, g_wproj);
    cudaGetSymbolAddress((void**)&p_wfc1,  g_wfc1);
    cudaGetSymbolAddress((void**)&p_wfc2,  g_wfc2);

    cudaFuncSetAttribute(attn_kernel, cudaFuncAttributeMaxDynamicSharedMemorySize, ATTN_SMEM);
    cudaFuncSetAttribute(gemm_mma<0>, cudaFuncAttributeMaxDynamicSharedMemorySize, GEMM_SMEM);
    cudaFuncSetAttribute(gemm_mma<1>, cudaFuncAttributeMaxDynamicSharedMemorySize, GEMM_SMEM);
    cudaFuncSetAttribute(gemm_mma<2>, cudaFuncAttributeMaxDynamicSharedMemorySize, GEMM_SMEM);
    cudaFuncSetAttribute(gemm_mma<3>, cudaFuncAttributeMaxDynamicSharedMemorySize, GEMM_SMEM);

    // weight conversions
    convert_w<<<(768*256 + 255)/256, 256>>>(qkvw,  p_wqkv, 768, 256, 3);
    convert_w<<<(256*256 + 255)/256, 256>>>(projw, p_wproj, 256, 256, 3);
    convert_w<<<(1024*256 + 255)/256, 256>>>(fc1w, p_wfc1, 1024, 256, 1);
    convert_w<<<(256*1024 + 255)/256, 256>>>(fc2w, p_wfc2, 256, 1024, 1);

    // 1. LN1 + roll + window partition -> 3-seg bf16
    ln_kernel<<<NTOK/8, 256>>>(x, p_xw, n1w, n1b, 0);
    // 2. QKV GEMM (3-seg, K3=768)
    gemm_mma<0><<<dim3(6, 392), 256, GEMM_SMEM>>>(p_xw, p_wqkv, qkvb, nullptr, p_qkv, nullptr, 768);
    // 3. windowed attention
    attn_kernel<<<BW_*HEADS, 128, ATTN_SMEM>>>(rpe);
    // 4. proj GEMM (3-seg) + reverse/roll + residual
    gemm_mma<2><<<dim3(2, 392), 256, GEMM_SMEM>>>(p_att, p_wproj, projb, x, p_x2, nullptr, 768);
    // 5. LN2 -> plain bf16
    ln_kernel<<<NTOK/8, 256>>>(p_x2, p_hn, n2w, n2b, 1);
    // 6. fc1 GEMM (plain bf16, K3=256) + GELU -> plain bf16
    gemm_mma<1><<<dim3(8, 392), 256, GEMM_SMEM>>>(p_hn, p_wfc1, fc1b, nullptr, nullptr, p_h3, 256);
    // 7. fc2 GEMM (plain bf16, K3=1024) + residual -> out
    gemm_mma<3><<<dim3(2, 392), 256, GEMM_SMEM>>>(p_h3, p_wfc2, fc2b, p_x2, out, nullptr, 1024);
}

// round 5
// speedup vs baseline: 3.7202x; 1.1271x over previous
#include <cuda_runtime.h>
#include <cuda_bf16.h>
#include <math.h>
#include <stdint.h>

// ---------------- problem constants ----------------
#define DIM   256
#define HEADS 8
#define HD    32
#define B_    2
#define T_    8
#define H_    56
#define W_    56
#define WT    2
#define WH    7
#define WW    7
#define STs   1
#define SHs   3
#define SWs   3
#define NTOK  (B_*T_*H_*W_)   // 50176 = 392*128
#define BW_   512
#define N_    98
#define HID   1024

// ---------------- scratch (device globals) ----------
__device__ __nv_bfloat16 g_xw [NTOK*512];          // LN1 2-seg [hi,lo]
__device__ float         g_qkv[(size_t)NTOK*768];
__device__ __nv_bfloat16 g_att[NTOK*512];          // attn out 2-seg
__device__ float         g_x2 [NTOK*256];          // residual-1
__device__ __nv_bfloat16 g_hn [NTOK*256];          // LN2 plain bf16
__device__ __nv_bfloat16 g_h3 [(size_t)NTOK*1024]; // fc1+gelu plain bf16
__device__ __nv_bfloat16 g_wqkv [768*512];         // 2-seg [hi,hi]
__device__ __nv_bfloat16 g_wproj[256*512];         // 2-seg [hi,hi]
__device__ __nv_bfloat16 g_wfc1 [1024*256];        // plain
__device__ __nv_bfloat16 g_wfc2 [256*1024];        // plain

// ---------------- PTX helpers ----------------------
__device__ __forceinline__ uint32_t smem_u32(const void* p) {
    uint32_t a;
    asm("{ .reg .u64 t; cvta.to.shared.u64 t, %1; cvt.u32.u64 %0, t; }" : "=r"(a) : "l"(p));
    return a;
}
#define CP_ASYNC16(sm, gp) \
    asm volatile("cp.async.cg.shared.global [%0], [%1], 16;" :: "r"(sm), "l"(gp))
#define CP_COMMIT() asm volatile("cp.async.commit_group;" ::: "memory")
#define CP_WAIT0()  asm volatile("cp.async.wait_group 0;" ::: "memory")
#define CP_WAIT1()  asm volatile("cp.async.wait_group 1;" ::: "memory")

// ---------------- bf16 store helpers ----------------
__device__ __forceinline__ uint32_t pack2(__nv_bfloat16 a, __nv_bfloat16 b) {
    return (uint32_t)__bfloat16_as_ushort(a) | ((uint32_t)__bfloat16_as_ushort(b) << 16);
}
// 2-seg activation: seg0=hi, seg1=lo (row stride 2K)
__device__ __forceinline__ void split_store4(__nv_bfloat16* rowp, int col, int K,
                                             float a0, float a1, float a2, float a3) {
    __nv_bfloat16 b0 = __float2bfloat16_rn(a0), b1 = __float2bfloat16_rn(a1);
    __nv_bfloat16 b2 = __float2bfloat16_rn(a2), b3 = __float2bfloat16_rn(a3);
    float l0 = a0 - __bfloat162float(b0), l1 = a1 - __bfloat162float(b1);
    float l2 = a2 - __bfloat162float(b2), l3 = a3 - __bfloat162float(b3);
    uint2 hiu; hiu.x = pack2(b0, b1); hiu.y = pack2(b2, b3);
    uint2 lou; lou.x = pack2(__float2bfloat16_rn(l0), __float2bfloat16_rn(l1));
    lou.y = pack2(__float2bfloat16_rn(l2), __float2bfloat16_rn(l3));
    *(uint2*)(rowp + col)     = hiu;
    *(uint2*)(rowp + K + col) = lou;
}
__device__ __forceinline__ void plain_store4(__nv_bfloat16* rowp, int col,
                                             float a0, float a1, float a2, float a3) {
    uint2 u;
    u.x = pack2(__float2bfloat16_rn(a0), __float2bfloat16_rn(a1));
    u.y = pack2(__float2bfloat16_rn(a2), __float2bfloat16_rn(a3));
    *(uint2*)(rowp + col) = u;
}

// ---------------- weight conversion -------------------
// segs==2: [hi, hi] (row stride 2K); segs==1: plain
__global__ void convert_w(const float* __restrict__ src, __nv_bfloat16* __restrict__ dst,
                          int Nn, int K, int segs) {
    int idx = blockIdx.x * 256 + threadIdx.x;
    if (idx >= Nn * K) return;
    int n = idx / K, k = idx % K;
    float v = src[idx];
    __nv_bfloat16 hi = __float2bfloat16_rn(v);
    if (segs == 2) {
        __nv_bfloat16* r = dst + (size_t)n * 2 * K;
        r[k]     = hi;
        r[K + k] = hi;
    } else {
        dst[(size_t)n * K + k] = hi;
    }
}

// ---------------- LN kernel (mode 0: +roll+partition -> 2-seg; mode 1: plain bf16)
__global__ void ln_kernel(const float* __restrict__ src, __nv_bfloat16* __restrict__ dst,
                          const float* __restrict__ w, const float* __restrict__ b, int mode) {
    int warp = threadIdx.x >> 5, lane = threadIdx.x & 31;
    int row = blockIdx.x * 8 + warp;
    const float* sr = src + (size_t)row * DIM;
    float4 v0 = *(const float4*)(sr + lane * 4);
    float4 v1 = *(const float4*)(sr + 128 + lane * 4);
    float s  = v0.x + v0.y + v0.z + v0.w + v1.x + v1.y + v1.z + v1.w;
    float ss = v0.x*v0.x + v0.y*v0.y + v0.z*v0.z + v0.w*v0.w
             + v1.x*v1.x + v1.y*v1.y + v1.z*v1.z + v1.w*v1.w;
    #pragma unroll
    for (int o = 16; o > 0; o >>= 1) {
        s  += __shfl_xor_sync(0xffffffffu, s, o);
        ss += __shfl_xor_sync(0xffffffffu, ss, o);
    }
    float mean = s * (1.0f / 256.0f);
    float var  = ss * (1.0f / 256.0f) - mean * mean;
    float inv  = rsqrtf(var + 1e-5f);
    int c0 = lane * 4, c1 = 128 + lane * 4;
    float o00 = (v0.x - mean) * inv * w[c0+0] + b[c0+0];
    float o01 = (v0.y - mean) * inv * w[c0+1] + b[c0+1];
    float o02 = (v0.z - mean) * inv * w[c0+2] + b[c0+2];
    float o03 = (v0.w - mean) * inv * w[c0+3] + b[c0+3];
    float o10 = (v1.x - mean) * inv * w[c1+0] + b[c1+0];
    float o11 = (v1.y - mean) * inv * w[c1+1] + b[c1+1];
    float o12 = (v1.z - mean) * inv * w[c1+2] + b[c1+2];
    float o13 = (v1.w - mean) * inv * w[c1+3] + b[c1+3];

    if (mode == 0) {
        int bb = row / (T_*H_*W_);
        int r2 = row % (T_*H_*W_);
        int t = r2 / (H_*W_);
        int r3 = r2 % (H_*W_);
        int h = r3 / W_, ww_ = r3 % W_;
        int t2 = t - STs; if (t2 < 0) t2 += T_;
        int h2 = h - SHs; if (h2 < 0) h2 += H_;
        int w2 = ww_ - SWs; if (w2 < 0) w2 += W_;
        int tw = t2 / WT, hw = h2 / WH, wwn = w2 / WW;
        int n = (t2 % WT) * 49 + (h2 % WH) * 7 + (w2 % WW);
        int bw = ((bb * 4 + tw) * 8 + hw) * 8 + wwn;
        __nv_bfloat16* dr = dst + ((size_t)bw * N_ + n) * 512;
        split_store4(dr, c0, 256, o00, o01, o02, o03);
        split_store4(dr, c1, 256, o10, o11, o12, o13);
    } else {
        __nv_bfloat16* dr = dst + (size_t)row * 256;
        plain_store4(dr, c0, o00, o01, o02, o03);
        plain_store4(dr, c1, o10, o11, o12, o13);
    }
}

// ---------------- mma.sync GEMM: C[M,Ncols] = A[M,K3]@W[Ncols,K3]^T --------
// block 128x128, 8 warps (2x4), warp tile 64x32, K-chunk 64,
// 3-stage cp.async pipeline, ONE __syncthreads per chunk.
// EPI 0: +bias -> fp32 (qkv)   EPI 1: +bias,GELU -> plain bf16 (fc1)
// EPI 2: +bias, reverse+roll remap, +resid -> fp32 (proj)
// EPI 3: +bias, +resid -> fp32 (fc2)
#define ABUF 18432           // 128 rows * 144B
#define BUFSZ (2*ABUF)       // A+B per stage = 36864
#define GEMM_SMEM (3*BUFSZ)  // 110592

template<int EPI>
__global__ __launch_bounds__(256) void gemm_mma(
        const __nv_bfloat16* __restrict__ A, const __nv_bfloat16* __restrict__ Wm,
        const float* __restrict__ bias, const float* __restrict__ resid,
        float* __restrict__ outF, __nv_bfloat16* __restrict__ outB, int K3) {
    extern __shared__ __align__(16) char smraw[];
    int tid = threadIdx.x, lane = tid & 31, wid = tid >> 5;
    int brow = blockIdx.y * 128, bcol = blockIdx.x * 128;
    int wm = wid & 1, wn = wid >> 1;
    uint32_t sb = smem_u32(smraw);

    float acc[4][4][4] = {};
    const int NC = K3 >> 6;

    const char* Agc = (const char*)(A  + (size_t)brow * K3);
    const char* Bgc = (const char*)(Wm + (size_t)bcol * K3);
    size_t rowstride = (size_t)K3 * 2;

    auto loadChunk = [&](int c, int buf) {
        uint32_t abase = sb + buf * BUFSZ;
        uint32_t bbase = abase + ABUF;
        const char* Ag = Agc + (size_t)c * 128;
        const char* Bg = Bgc + (size_t)c * 128;
        #pragma unroll
        for (int j = 0; j < 4; j++) {
            int x = tid + j * 256;
            int row = x >> 3, kc = x & 7;
            CP_ASYNC16(abase + row * 144 + kc * 16, Ag + (size_t)row * rowstride + kc * 16);
            CP_ASYNC16(bbase + row * 144 + kc * 16, Bg + (size_t)row * rowstride + kc * 16);
        }
        CP_COMMIT();
    };

    loadChunk(0, 0);
    loadChunk(1, 1);
    int bc = 0, bn2 = 2;
    for (int c = 0; c < NC; c++) {
        if (c + 1 < NC) CP_WAIT1(); else CP_WAIT0();
        __syncthreads();                       // chunk c data visible; chunk c-1 compute finished
        if (c + 2 < NC) loadChunk(c + 2, bn2); // refill buffer freed by chunk c-1
        uint32_t abase = sb + bc * BUFSZ;
        uint32_t bbase = abase + ABUF;
        #pragma unroll
        for (int kh = 0; kh < 4; kh++) {
            uint32_t afr[4][4];
            #pragma unroll
            for (int mt = 0; mt < 4; mt++) {
                int row = wm * 64 + mt * 16 + ((lane >> 3) & 1) * 8 + (lane & 7);
                uint32_t addr = abase + row * 144 + kh * 32 + (lane >> 4) * 16;
                asm volatile("ldmatrix.sync.aligned.m8n8.x4.shared.b16 {%0,%1,%2,%3}, [%4];"
                    : "=r"(afr[mt][0]), "=r"(afr[mt][1]), "=r"(afr[mt][2]), "=r"(afr[mt][3])
                    : "r"(addr));
            }
            uint32_t bfr[4][2];
            #pragma unroll
            for (int np = 0; np < 2; np++) {
                int nrow = wn * 32 + np * 16 + (lane >> 4) * 8 + (lane & 7);
                uint32_t addr = bbase + nrow * 144 + kh * 32 + ((lane >> 3) & 1) * 16;
                uint32_t r0, r1, r2, r3;
                asm volatile("ldmatrix.sync.aligned.m8n8.x4.shared.b16 {%0,%1,%2,%3}, [%4];"
                    : "=r"(r0), "=r"(r1), "=r"(r2), "=r"(r3) : "r"(addr));
                bfr[np*2][0] = r0; bfr[np*2][1] = r1;
                bfr[np*2+1][0] = r2; bfr[np*2+1][1] = r3;
            }
            #pragma unroll
            for (int mt = 0; mt < 4; mt++)
                #pragma unroll
                for (int nt = 0; nt < 4; nt++)
                    asm volatile(
                        "mma.sync.aligned.m16n8k16.row.col.f32.bf16.bf16.f32 "
                        "{%0,%1,%2,%3}, {%4,%5,%6,%7}, {%8,%9}, {%0,%1,%2,%3};"
                        : "+f"(acc[mt][nt][0]), "+f"(acc[mt][nt][1]),
                          "+f"(acc[mt][nt][2]), "+f"(acc[mt][nt][3])
                        : "r"(afr[mt][0]), "r"(afr[mt][1]), "r"(afr[mt][2]), "r"(afr[mt][3]),
                          "r"(bfr[nt][0]), "r"(bfr[nt][1]));
        }
        bc++;  if (bc == 3)  bc = 0;
        bn2++; if (bn2 == 3) bn2 = 0;
    }
    __syncthreads();

    // ---- epilogue: accs -> SMEM (stride 132 f32) -> coalesced stores ----
    float* Cs = (float*)smraw;
    #pragma unroll
    for (int mt = 0; mt < 4; mt++)
        #pragma unroll
        for (int nt = 0; nt < 4; nt++) {
            int r0 = wm * 64 + mt * 16 + (lane >> 2);
            int cc = wn * 32 + nt * 8 + (lane & 3) * 2;
            Cs[r0 * 132 + cc]       = acc[mt][nt][0];
            Cs[r0 * 132 + cc + 1]   = acc[mt][nt][1];
            Cs[(r0+8) * 132 + cc]   = acc[mt][nt][2];
            Cs[(r0+8) * 132 + cc+1] = acc[mt][nt][3];
        }
    __syncthreads();

    float4 bs = *(const float4*)(bias + bcol + lane * 4);
    for (int r = wid; r < 128; r += 8) {
        float4 v = *(const float4*)&Cs[r * 132 + lane * 4];
        v.x += bs.x; v.y += bs.y; v.z += bs.z; v.w += bs.w;
        int grow = brow + r;
        int col = bcol + lane * 4;
        if (EPI == 0) {
            *(float4*)(outF + (size_t)grow * 768 + col) = v;
        } else if (EPI == 1) {
            float g0 = 0.5f * v.x * (1.0f + erff(v.x * 0.70710678118654752f));
            float g1 = 0.5f * v.y * (1.0f + erff(v.y * 0.70710678118654752f));
            float g2 = 0.5f * v.z * (1.0f + erff(v.z * 0.70710678118654752f));
            float g3 = 0.5f * v.w * (1.0f + erff(v.w * 0.70710678118654752f));
            plain_store4(outB + (size_t)grow * 1024, col, g0, g1, g2, g3);
        } else if (EPI == 2) {
            int bw = grow / N_, n = grow % N_;
            int bb = bw >> 8, wrem = bw & 255;
            int tw = wrem >> 6, hw = (wrem >> 3) & 7, wwn = wrem & 7;
            int nt = n / 49, nr = n % 49;
            int t2 = tw*WT + nt, h2 = hw*WH + nr/7, w2 = wwn*WW + nr%7;
            int t = t2 + STs; if (t >= T_) t -= T_;
            int h = h2 + SHs; if (h >= H_) h -= H_;
            int ww_ = w2 + SWs; if (ww_ >= W_) ww_ -= W_;
            size_t orow = ((size_t)((bb*T_ + t)*H_ + h))*W_ + ww_;
            float4 rr = *(const float4*)(resid + orow * 256 + col);
            v.x += rr.x; v.y += rr.y; v.z += rr.z; v.w += rr.w;
            *(float4*)(outF + orow * 256 + col) = v;
        } else {
            float4 rr = *(const float4*)(resid + (size_t)grow * 256 + col);
            v.x += rr.x; v.y += rr.y; v.z += rr.z; v.w += rr.w;
            *(float4*)(outF + (size_t)grow * 256 + col) = v;
        }
    }
}

// ---------------- attention: one block per (window, head) ------------------
__global__ __launch_bounds__(128) void attn_kernel(const float* __restrict__ rpe) {
    extern __shared__ float sm[];
    float* ks = sm;                  // 98*32
    float* vs = sm + 98*32;          // 98*32
    float* ps = sm + 2*98*32;        // 98*99
    int*   tc = (int*)(ps + 98*99);  // 98

    int bid  = blockIdx.x;
    int head = bid & 7;
    int bw   = bid >> 3;
    int wrem = bw & 255;
    int tw = wrem >> 6, hw = (wrem >> 3) & 7, wwn = wrem & 7;
    int tid = threadIdx.x;

    const float* qbase = g_qkv + ((size_t)bw * N_) * 768 + head * HD;
    for (int i = tid; i < N_*HD; i += 128) {
        int m = i >> 5, d = i & 31;
        size_t o = (size_t)m * 768 + d;
        ks[i] = qbase[o + 256];
        vs[i] = qbase[o + 512];
    }
    if (tid < N_) {
        int t = tid / 49, rem = tid % 49, h = rem / 7, w = rem % 7;
        int gt = tw*WT + t, gh = hw*WH + h, gw = wwn*WW + w;
        int rt = (gt < T_-WT) ? 0 : ((gt < T_-STs) ? 1 : 2);
        int rh = (gh < H_-WH) ? 0 : ((gh < H_-SHs) ? 1 : 2);
        int rw = (gw < W_-WW) ? 0 : ((gw < W_-SWs) ? 1 : 2);
        tc[tid] = t | (h << 4) | (w << 8) | ((rt*9 + rh*3 + rw) << 12);
    }
    __syncthreads();

    if (tid < N_) {
        int r = tid;
        int pc = tc[r];
        int tr = pc & 15, hr = (pc >> 4) & 15, wr = (pc >> 8) & 15, regr = pc >> 12;
        float4 q4[8];
        const float4* qg = (const float4*)(qbase + (size_t)r * 768);
        #pragma unroll
        for (int i = 0; i < 8; i++) {
            q4[i] = qg[i];
            q4[i].x *= 0.17677669529663687f; q4[i].y *= 0.17677669529663687f;
            q4[i].z *= 0.17677669529663687f; q4[i].w *= 0.17677669529663687f;
        }

        float* prow = ps + r*99;
        float mx = -1e30f;
        for (int m = 0; m < N_; m++) {
            const float4* k4 = (const float4*)(ks + m*HD);
            float s0 = 0.f, s1 = 0.f, s2 = 0.f, s3 = 0.f;
            #pragma unroll
            for (int i = 0; i < 8; i++) {
                float4 kk = k4[i];
                s0 = fmaf(q4[i].x, kk.x, s0);
                s1 = fmaf(q4[i].y, kk.y, s1);
                s2 = fmaf(q4[i].z, kk.z, s2);
                s3 = fmaf(q4[i].w, kk.w, s3);
            }
            float s = (s0 + s1) + (s2 + s3);
            int pm = tc[m];
            int idx = (tr - (pm & 15) + (WT-1)) * ((2*WH-1)*(2*WW-1))
                    + (hr - ((pm >> 4) & 15) + (WH-1)) * (2*WW-1)
                    + (wr - ((pm >> 8) & 15) + (WW-1));
            s += __ldg(&rpe[idx * HEADS + head]);
            if (regr != (pm >> 12)) s -= 100.0f;
            prow[m] = s;
            mx = fmaxf(mx, s);
        }
        float sum = 0.f;
        for (int m = 0; m < N_; m++) {
            float e = __expf(prow[m] - mx);
            prow[m] = e;
            sum += e;
        }
        float invs = 1.0f / sum;

        float4 acc[8];
        #pragma unroll
        for (int i = 0; i < 8; i++) acc[i] = make_float4(0.f, 0.f, 0.f, 0.f);
        for (int m = 0; m < N_; m++) {
            float p = prow[m];
            const float4* v4 = (const float4*)(vs + m*HD);
            #pragma unroll
            for (int i = 0; i < 8; i++) {
                float4 vv = v4[i];
                acc[i].x = fmaf(p, vv.x, acc[i].x);
                acc[i].y = fmaf(p, vv.y, acc[i].y);
                acc[i].z = fmaf(p, vv.z, acc[i].z);
                acc[i].w = fmaf(p, vv.w, acc[i].w);
            }
        }
        __nv_bfloat16* orow = g_att + ((size_t)(bw*N_ + r)) * 512;
        #pragma unroll
        for (int i = 0; i < 8; i++) {
            split_store4(orow, head*HD + i*4, 256,
                acc[i].x*invs, acc[i].y*invs, acc[i].z*invs, acc[i].w*invs);
        }
    }
}
#define ATTN_SMEM ((2*98*32 + 98*99) * 4 + 98 * 4)

// ---------------- host launcher ---------------------------------------------
extern "C" void kernel_launch(void* const* d_in, const int* in_sizes, int n_in,
                              void* d_out, int out_size) {
    const float* x     = (const float*)d_in[0];
    const float* n1w   = (const float*)d_in[1];
    const float* n1b   = (const float*)d_in[2];
    const float* qkvw  = (const float*)d_in[3];
    const float* qkvb  = (const float*)d_in[4];
    const float* projw = (const float*)d_in[5];
    const float* projb = (const float*)d_in[6];
    const float* rpe   = (const float*)d_in[7];
    const float* n2w   = (const float*)d_in[8];
    const float* n2b   = (const float*)d_in[9];
    const float* fc1w  = (const float*)d_in[10];
    const float* fc1b  = (const float*)d_in[11];
    const float* fc2w  = (const float*)d_in[12];
    const float* fc2b  = (const float*)d_in[13];
    float* out = (float*)d_out;

    __nv_bfloat16 *p_xw, *p_att, *p_hn, *p_h3, *p_wqkv, *p_wproj, *p_wfc1, *p_wfc2;
    float *p_qkv, *p_x2;
    cudaGetSymbolAddress((void**)&p_xw,  g_xw);
    cudaGetSymbolAddress((void**)&p_qkv, g_qkv);
    cudaGetSymbolAddress((void**)&p_att, g_att);
    cudaGetSymbolAddress((void**)&p_x2,  g_x2);
    cudaGetSymbolAddress((void**)&p_hn,  g_hn);
    cudaGetSymbolAddress((void**)&p_h3,  g_h3);
    cudaGetSymbolAddress((void**)&p_wqkv,  g_wqkv);
    cudaGetSymbolAddress((void**)&p_wproj, g_wproj);
    cudaGetSymbolAddress((void**)&p_wfc1,  g_wfc1);
    cudaGetSymbolAddress((void**)&p_wfc2,  g_wfc2);

    cudaFuncSetAttribute(attn_kernel, cudaFuncAttributeMaxDynamicSharedMemorySize, ATTN_SMEM);
    cudaFuncSetAttribute(gemm_mma<0>, cudaFuncAttributeMaxDynamicSharedMemorySize, GEMM_SMEM);
    cudaFuncSetAttribute(gemm_mma<1>, cudaFuncAttributeMaxDynamicSharedMemorySize, GEMM_SMEM);
    cudaFuncSetAttribute(gemm_mma<2>, cudaFuncAttributeMaxDynamicSharedMemorySize, GEMM_SMEM);
    cudaFuncSetAttribute(gemm_mma<3>, cudaFuncAttributeMaxDynamicSharedMemorySize, GEMM_SMEM);

    // weight conversions
    convert_w<<<(768*256 + 255)/256, 256>>>(qkvw,  p_wqkv, 768, 256, 2);
    convert_w<<<(256*256 + 255)/256, 256>>>(projw, p_wproj, 256, 256, 2);
    convert_w<<<(1024*256 + 255)/256, 256>>>(fc1w, p_wfc1, 1024, 256, 1);
    convert_w<<<(256*1024 + 255)/256, 256>>>(fc2w, p_wfc2, 256, 1024, 1);

    // 1. LN1 + roll + window partition -> 2-seg bf16
    ln_kernel<<<NTOK/8, 256>>>(x, p_xw, n1w, n1b, 0);
    // 2. QKV GEMM (2-seg, K3=512)
    gemm_mma<0><<<dim3(6, 392), 256, GEMM_SMEM>>>(p_xw, p_wqkv, qkvb, nullptr, p_qkv, nullptr, 512);
    // 3. windowed attention
    attn_kernel<<<BW_*HEADS, 128, ATTN_SMEM>>>(rpe);
    // 4. proj GEMM (2-seg) + reverse/roll + residual
    gemm_mma<2><<<dim3(2, 392), 256, GEMM_SMEM>>>(p_att, p_wproj, projb, x, p_x2, nullptr, 512);
    // 5. LN2 -> plain bf16
    ln_kernel<<<NTOK/8, 256>>>(p_x2, p_hn, n2w, n2b, 1);
    // 6. fc1 GEMM (plain bf16, K3=256) + GELU -> plain bf16
    gemm_mma<1><<<dim3(8, 392), 256, GEMM_SMEM>>>(p_hn, p_wfc1, fc1b, nullptr, nullptr, p_h3, 256);
    // 7. fc2 GEMM (plain bf16, K3=1024) + residual -> out
    gemm_mma<3><<<dim3(2, 392), 256, GEMM_SMEM>>>(p_h3, p_wfc2, fc2b, p_x2, out, nullptr, 1024);
}

// round 6
// speedup vs baseline: 4.3751x; 1.1760x over previous
#include <cuda_runtime.h>
#include <cuda_bf16.h>
#include <math.h>
#include <stdint.h>

// ---------------- problem constants ----------------
#define DIM   256
#define HEADS 8
#define HD    32
#define B_    2
#define T_    8
#define H_    56
#define W_    56
#define WT    2
#define WH    7
#define WW    7
#define STs   1
#define SHs   3
#define SWs   3
#define NTOK  (B_*T_*H_*W_)   // 50176 = 392*128
#define BW_   512
#define N_    98
#define HID   1024

// ---------------- scratch (device globals) ----------
__device__ __nv_bfloat16 g_xw [NTOK*512];          // LN1 2-seg [hi,lo]
__device__ __nv_bfloat16 g_qkv[(size_t)NTOK*768];  // qkv plain bf16
__device__ __nv_bfloat16 g_att[NTOK*512];          // attn out 2-seg
__device__ float         g_x2 [NTOK*256];          // residual-1
__device__ __nv_bfloat16 g_hn [NTOK*256];          // LN2 plain bf16
__device__ __nv_bfloat16 g_h3 [(size_t)NTOK*1024]; // fc1+gelu plain bf16
__device__ __nv_bfloat16 g_wqkv [768*512];         // 2-seg [hi,hi]
__device__ __nv_bfloat16 g_wproj[256*512];         // 2-seg [hi,hi]
__device__ __nv_bfloat16 g_wfc1 [1024*256];        // plain
__device__ __nv_bfloat16 g_wfc2 [256*1024];        // plain
__device__ float         g_bias[HEADS*N_*N_];      // precomputed rpe bias

// ---------------- PTX helpers ----------------------
__device__ __forceinline__ uint32_t smem_u32(const void* p) {
    uint32_t a;
    asm("{ .reg .u64 t; cvta.to.shared.u64 t, %1; cvt.u32.u64 %0, t; }" : "=r"(a) : "l"(p));
    return a;
}
#define CP_ASYNC16(sm, gp) \
    asm volatile("cp.async.cg.shared.global [%0], [%1], 16;" :: "r"(sm), "l"(gp))
#define CP_COMMIT() asm volatile("cp.async.commit_group;" ::: "memory")
#define CP_WAIT0()  asm volatile("cp.async.wait_group 0;" ::: "memory")
#define CP_WAIT1()  asm volatile("cp.async.wait_group 1;" ::: "memory")

#define LDMATRIX_X4(r0,r1,r2,r3,addr) \
    asm volatile("ldmatrix.sync.aligned.m8n8.x4.shared.b16 {%0,%1,%2,%3}, [%4];" \
        : "=r"(r0), "=r"(r1), "=r"(r2), "=r"(r3) : "r"(addr))
#define LDMATRIX_X4T(r0,r1,r2,r3,addr) \
    asm volatile("ldmatrix.sync.aligned.m8n8.x4.trans.shared.b16 {%0,%1,%2,%3}, [%4];" \
        : "=r"(r0), "=r"(r1), "=r"(r2), "=r"(r3) : "r"(addr))
#define MMA_BF16(c, a, b) \
    asm volatile("mma.sync.aligned.m16n8k16.row.col.f32.bf16.bf16.f32 " \
        "{%0,%1,%2,%3}, {%4,%5,%6,%7}, {%8,%9}, {%0,%1,%2,%3};" \
        : "+f"((c)[0]), "+f"((c)[1]), "+f"((c)[2]), "+f"((c)[3]) \
        : "r"((a)[0]), "r"((a)[1]), "r"((a)[2]), "r"((a)[3]), "r"((b)[0]), "r"((b)[1]))

// ---------------- bf16 store helpers ----------------
__device__ __forceinline__ uint32_t pack2(__nv_bfloat16 a, __nv_bfloat16 b) {
    return (uint32_t)__bfloat16_as_ushort(a) | ((uint32_t)__bfloat16_as_ushort(b) << 16);
}
__device__ __forceinline__ void split_store4(__nv_bfloat16* rowp, int col, int K,
                                             float a0, float a1, float a2, float a3) {
    __nv_bfloat16 b0 = __float2bfloat16_rn(a0), b1 = __float2bfloat16_rn(a1);
    __nv_bfloat16 b2 = __float2bfloat16_rn(a2), b3 = __float2bfloat16_rn(a3);
    float l0 = a0 - __bfloat162float(b0), l1 = a1 - __bfloat162float(b1);
    float l2 = a2 - __bfloat162float(b2), l3 = a3 - __bfloat162float(b3);
    uint2 hiu; hiu.x = pack2(b0, b1); hiu.y = pack2(b2, b3);
    uint2 lou; lou.x = pack2(__float2bfloat16_rn(l0), __float2bfloat16_rn(l1));
    lou.y = pack2(__float2bfloat16_rn(l2), __float2bfloat16_rn(l3));
    *(uint2*)(rowp + col)     = hiu;
    *(uint2*)(rowp + K + col) = lou;
}
__device__ __forceinline__ void split_store2(__nv_bfloat16* rowp, int col,
                                             float a0, float a1) {
    __nv_bfloat16 b0 = __float2bfloat16_rn(a0), b1 = __float2bfloat16_rn(a1);
    float l0 = a0 - __bfloat162float(b0), l1 = a1 - __bfloat162float(b1);
    *(uint32_t*)(rowp + col)       = pack2(b0, b1);
    *(uint32_t*)(rowp + 256 + col) = pack2(__float2bfloat16_rn(l0), __float2bfloat16_rn(l1));
}
__device__ __forceinline__ void plain_store4(__nv_bfloat16* rowp, int col,
                                             float a0, float a1, float a2, float a3) {
    uint2 u;
    u.x = pack2(__float2bfloat16_rn(a0), __float2bfloat16_rn(a1));
    u.y = pack2(__float2bfloat16_rn(a2), __float2bfloat16_rn(a3));
    *(uint2*)(rowp + col) = u;
}

// ---------------- weight conversion -------------------
__global__ void convert_w(const float* __restrict__ src, __nv_bfloat16* __restrict__ dst,
                          int Nn, int K, int segs) {
    int idx = blockIdx.x * 256 + threadIdx.x;
    if (idx >= Nn * K) return;
    int n = idx / K, k = idx % K;
    float v = src[idx];
    __nv_bfloat16 hi = __float2bfloat16_rn(v);
    if (segs == 2) {
        __nv_bfloat16* r = dst + (size_t)n * 2 * K;
        r[k]     = hi;
        r[K + k] = hi;
    } else {
        dst[(size_t)n * K + k] = hi;
    }
}

// ---------------- rpe bias table: g_bias[h][r][m] ------------
__global__ void build_bias(const float* __restrict__ rpe) {
    int i = blockIdx.x * 128 + threadIdx.x;
    if (i >= N_*N_) return;
    int r = i / N_, m = i % N_;
    int tr = r / 49, hr = (r % 49) / 7, wr = r % 7;
    int tm = m / 49, hm = (m % 49) / 7, wm = m % 7;
    int idx = (tr - tm + (WT-1)) * ((2*WH-1)*(2*WW-1))
            + (hr - hm + (WH-1)) * (2*WW-1)
            + (wr - wm + (WW-1));
    #pragma unroll
    for (int h = 0; h < HEADS; h++)
        g_bias[h*N_*N_ + i] = rpe[idx*HEADS + h];
}

// ---------------- LN kernel --------------------------------
__global__ void ln_kernel(const float* __restrict__ src, __nv_bfloat16* __restrict__ dst,
                          const float* __restrict__ w, const float* __restrict__ b, int mode) {
    int warp = threadIdx.x >> 5, lane = threadIdx.x & 31;
    int row = blockIdx.x * 8 + warp;
    const float* sr = src + (size_t)row * DIM;
    float4 v0 = *(const float4*)(sr + lane * 4);
    float4 v1 = *(const float4*)(sr + 128 + lane * 4);
    float s  = v0.x + v0.y + v0.z + v0.w + v1.x + v1.y + v1.z + v1.w;
    float ss = v0.x*v0.x + v0.y*v0.y + v0.z*v0.z + v0.w*v0.w
             + v1.x*v1.x + v1.y*v1.y + v1.z*v1.z + v1.w*v1.w;
    #pragma unroll
    for (int o = 16; o > 0; o >>= 1) {
        s  += __shfl_xor_sync(0xffffffffu, s, o);
        ss += __shfl_xor_sync(0xffffffffu, ss, o);
    }
    float mean = s * (1.0f / 256.0f);
    float var  = ss * (1.0f / 256.0f) - mean * mean;
    float inv  = rsqrtf(var + 1e-5f);
    int c0 = lane * 4, c1 = 128 + lane * 4;
    float o00 = (v0.x - mean) * inv * w[c0+0] + b[c0+0];
    float o01 = (v0.y - mean) * inv * w[c0+1] + b[c0+1];
    float o02 = (v0.z - mean) * inv * w[c0+2] + b[c0+2];
    float o03 = (v0.w - mean) * inv * w[c0+3] + b[c0+3];
    float o10 = (v1.x - mean) * inv * w[c1+0] + b[c1+0];
    float o11 = (v1.y - mean) * inv * w[c1+1] + b[c1+1];
    float o12 = (v1.z - mean) * inv * w[c1+2] + b[c1+2];
    float o13 = (v1.w - mean) * inv * w[c1+3] + b[c1+3];

    if (mode == 0) {
        int bb = row / (T_*H_*W_);
        int r2 = row % (T_*H_*W_);
        int t = r2 / (H_*W_);
        int r3 = r2 % (H_*W_);
        int h = r3 / W_, ww_ = r3 % W_;
        int t2 = t - STs; if (t2 < 0) t2 += T_;
        int h2 = h - SHs; if (h2 < 0) h2 += H_;
        int w2 = ww_ - SWs; if (w2 < 0) w2 += W_;
        int tw = t2 / WT, hw = h2 / WH, wwn = w2 / WW;
        int n = (t2 % WT) * 49 + (h2 % WH) * 7 + (w2 % WW);
        int bw = ((bb * 4 + tw) * 8 + hw) * 8 + wwn;
        __nv_bfloat16* dr = dst + ((size_t)bw * N_ + n) * 512;
        split_store4(dr, c0, 256, o00, o01, o02, o03);
        split_store4(dr, c1, 256, o10, o11, o12, o13);
    } else {
        __nv_bfloat16* dr = dst + (size_t)row * 256;
        plain_store4(dr, c0, o00, o01, o02, o03);
        plain_store4(dr, c1, o10, o11, o12, o13);
    }
}

// ---------------- mma.sync GEMM ----------------------------
// EPI 0: +bias -> plain bf16 stride 768 (qkv)
// EPI 1: +bias,GELU -> plain bf16 stride 1024 (fc1)
// EPI 2: +bias, reverse+roll remap, +resid -> fp32 (proj)
// EPI 3: +bias, +resid -> fp32 (fc2)
#define ABUF 18432
#define BUFSZ (2*ABUF)
#define GEMM_SMEM (3*BUFSZ)

template<int EPI>
__global__ __launch_bounds__(256) void gemm_mma(
        const __nv_bfloat16* __restrict__ A, const __nv_bfloat16* __restrict__ Wm,
        const float* __restrict__ bias, const float* __restrict__ resid,
        float* __restrict__ outF, __nv_bfloat16* __restrict__ outB, int K3) {
    extern __shared__ __align__(16) char smraw[];
    int tid = threadIdx.x, lane = tid & 31, wid = tid >> 5;
    int brow = blockIdx.y * 128, bcol = blockIdx.x * 128;
    int wm = wid & 1, wn = wid >> 1;
    uint32_t sb = smem_u32(smraw);

    float acc[4][4][4] = {};
    const int NC = K3 >> 6;

    const char* Agc = (const char*)(A  + (size_t)brow * K3);
    const char* Bgc = (const char*)(Wm + (size_t)bcol * K3);
    size_t rowstride = (size_t)K3 * 2;

    auto loadChunk = [&](int c, int buf) {
        uint32_t abase = sb + buf * BUFSZ;
        uint32_t bbase = abase + ABUF;
        const char* Ag = Agc + (size_t)c * 128;
        const char* Bg = Bgc + (size_t)c * 128;
        #pragma unroll
        for (int j = 0; j < 4; j++) {
            int x = tid + j * 256;
            int row = x >> 3, kc = x & 7;
            CP_ASYNC16(abase + row * 144 + kc * 16, Ag + (size_t)row * rowstride + kc * 16);
            CP_ASYNC16(bbase + row * 144 + kc * 16, Bg + (size_t)row * rowstride + kc * 16);
        }
        CP_COMMIT();
    };

    loadChunk(0, 0);
    loadChunk(1, 1);
    int bc = 0, bn2 = 2;
    for (int c = 0; c < NC; c++) {
        if (c + 1 < NC) CP_WAIT1(); else CP_WAIT0();
        __syncthreads();
        if (c + 2 < NC) loadChunk(c + 2, bn2);
        uint32_t abase = sb + bc * BUFSZ;
        uint32_t bbase = abase + ABUF;
        #pragma unroll
        for (int kh = 0; kh < 4; kh++) {
            uint32_t afr[4][4];
            #pragma unroll
            for (int mt = 0; mt < 4; mt++) {
                int row = wm * 64 + mt * 16 + ((lane >> 3) & 1) * 8 + (lane & 7);
                uint32_t addr = abase + row * 144 + kh * 32 + (lane >> 4) * 16;
                LDMATRIX_X4(afr[mt][0], afr[mt][1], afr[mt][2], afr[mt][3], addr);
            }
            uint32_t bfr[4][2];
            #pragma unroll
            for (int np = 0; np < 2; np++) {
                int nrow = wn * 32 + np * 16 + (lane >> 4) * 8 + (lane & 7);
                uint32_t addr = bbase + nrow * 144 + kh * 32 + ((lane >> 3) & 1) * 16;
                uint32_t r0, r1, r2, r3;
                LDMATRIX_X4(r0, r1, r2, r3, addr);
                bfr[np*2][0] = r0; bfr[np*2][1] = r1;
                bfr[np*2+1][0] = r2; bfr[np*2+1][1] = r3;
            }
            #pragma unroll
            for (int mt = 0; mt < 4; mt++)
                #pragma unroll
                for (int nt = 0; nt < 4; nt++)
                    MMA_BF16(acc[mt][nt], afr[mt], bfr[nt]);
        }
        bc++;  if (bc == 3)  bc = 0;
        bn2++; if (bn2 == 3) bn2 = 0;
    }
    __syncthreads();

    float* Cs = (float*)smraw;
    #pragma unroll
    for (int mt = 0; mt < 4; mt++)
        #pragma unroll
        for (int nt = 0; nt < 4; nt++) {
            int r0 = wm * 64 + mt * 16 + (lane >> 2);
            int cc = wn * 32 + nt * 8 + (lane & 3) * 2;
            Cs[r0 * 132 + cc]       = acc[mt][nt][0];
            Cs[r0 * 132 + cc + 1]   = acc[mt][nt][1];
            Cs[(r0+8) * 132 + cc]   = acc[mt][nt][2];
            Cs[(r0+8) * 132 + cc+1] = acc[mt][nt][3];
        }
    __syncthreads();

    float4 bs = *(const float4*)(bias + bcol + lane * 4);
    for (int r = wid; r < 128; r += 8) {
        float4 v = *(const float4*)&Cs[r * 132 + lane * 4];
        v.x += bs.x; v.y += bs.y; v.z += bs.z; v.w += bs.w;
        int grow = brow + r;
        int col = bcol + lane * 4;
        if (EPI == 0) {
            plain_store4(outB + (size_t)grow * 768, col, v.x, v.y, v.z, v.w);
        } else if (EPI == 1) {
            float g0 = 0.5f * v.x * (1.0f + erff(v.x * 0.70710678118654752f));
            float g1 = 0.5f * v.y * (1.0f + erff(v.y * 0.70710678118654752f));
            float g2 = 0.5f * v.z * (1.0f + erff(v.z * 0.70710678118654752f));
            float g3 = 0.5f * v.w * (1.0f + erff(v.w * 0.70710678118654752f));
            plain_store4(outB + (size_t)grow * 1024, col, g0, g1, g2, g3);
        } else if (EPI == 2) {
            int bw = grow / N_, n = grow % N_;
            int bb = bw >> 8, wrem = bw & 255;
            int tw = wrem >> 6, hw = (wrem >> 3) & 7, wwn = wrem & 7;
            int nt = n / 49, nr = n % 49;
            int t2 = tw*WT + nt, h2 = hw*WH + nr/7, w2 = wwn*WW + nr%7;
            int t = t2 + STs; if (t >= T_) t -= T_;
            int h = h2 + SHs; if (h >= H_) h -= H_;
            int ww_ = w2 + SWs; if (ww_ >= W_) ww_ -= W_;
            size_t orow = ((size_t)((bb*T_ + t)*H_ + h))*W_ + ww_;
            float4 rr = *(const float4*)(resid + orow * 256 + col);
            v.x += rr.x; v.y += rr.y; v.z += rr.z; v.w += rr.w;
            *(float4*)(outF + orow * 256 + col) = v;
        } else {
            float4 rr = *(const float4*)(resid + (size_t)grow * 256 + col);
            v.x += rr.x; v.y += rr.y; v.z += rr.z; v.w += rr.w;
            *(float4*)(outF + (size_t)grow * 256 + col) = v;
        }
    }
}

// ---------------- tensor-core attention ---------------------
// one block per (window, head): QK^T mma, scalar softmax with precomputed
// bias, AV mma with ldmatrix.trans on V.
#define QSTR 80    // bytes/row Q,K,V smem (112 rows)
#define PSTR 240   // bytes/row P smem (112 rows x 112 cols bf16)
#define SSTR 114   // floats/row S (112 rows)
#define SM_Q  0
#define SM_K  (112*QSTR)
#define SM_V  (2*112*QSTR)
#define SM_P  (3*112*QSTR)
#define SM_S  (SM_P + 112*PSTR)
#define SM_TC (SM_S + 112*SSTR*4)
#define ATTN_SMEM (SM_TC + 112*4)

__global__ __launch_bounds__(128) void attn_tc() {
    extern __shared__ __align__(16) char asmem[];
    float* S = (float*)(asmem + SM_S);
    int* tc  = (int*)(asmem + SM_TC);

    int tid = threadIdx.x, lane = tid & 31, wid = tid >> 5;
    int head = blockIdx.x & 7, bw = blockIdx.x >> 3;
    int wrem = bw & 255;
    int tw = wrem >> 6, hw = (wrem >> 3) & 7, wwn = wrem & 7;

    uint32_t uQ = smem_u32(asmem + SM_Q);
    uint32_t uK = smem_u32(asmem + SM_K);
    uint32_t uV = smem_u32(asmem + SM_V);
    uint32_t uP = smem_u32(asmem + SM_P);

    // ---- load q,k,v rows (bf16) ----
    if (tid < N_) {
        const uint4* g = (const uint4*)(g_qkv + ((size_t)(bw*N_ + tid)) * 768 + head * HD);
        #pragma unroll
        for (int j = 0; j < 4; j++) {
            *(uint4*)(asmem + SM_Q + tid*QSTR + j*16) = g[j];
            *(uint4*)(asmem + SM_K + tid*QSTR + j*16) = g[32 + j];
            *(uint4*)(asmem + SM_V + tid*QSTR + j*16) = g[64 + j];
        }
        int t = tid / 49, rem = tid % 49, h = rem / 7, w = rem % 7;
        int gt = tw*WT + t, gh = hw*WH + h, gw = wwn*WW + w;
        int rt = (gt < T_-WT) ? 0 : ((gt < T_-STs) ? 1 : 2);
        int rh = (gh < H_-WH) ? 0 : ((gh < H_-SHs) ? 1 : 2);
        int rw = (gw < W_-WW) ? 0 : ((gw < W_-SWs) ? 1 : 2);
        tc[tid] = rt*9 + rh*3 + rw;
    } else if (tid < 112) {
        // zero V pad rows (multiplied by zeroed P cols; must be finite)
        uint4 z = make_uint4(0,0,0,0);
        #pragma unroll
        for (int j = 0; j < 4; j++)
            *(uint4*)(asmem + SM_V + tid*QSTR + j*16) = z;
    }
    __syncthreads();

    int nmt = (wid < 3) ? 2 : 1;

    // ---- QK^T: acc[mtl][nt] over 14 n8-tiles, K=32 (2 k16) ----
    {
        float acc[2][14][4] = {};
        #pragma unroll
        for (int kh = 0; kh < 2; kh++) {
            uint32_t bfr[14][2];
            #pragma unroll
            for (int np = 0; np < 7; np++) {
                int nrow = np*16 + (lane >> 4) * 8 + (lane & 7);
                uint32_t addr = uK + nrow*QSTR + kh*32 + ((lane >> 3) & 1) * 16;
                uint32_t r0, r1, r2, r3;
                LDMATRIX_X4(r0, r1, r2, r3, addr);
                bfr[np*2][0] = r0; bfr[np*2][1] = r1;
                bfr[np*2+1][0] = r2; bfr[np*2+1][1] = r3;
            }
            for (int mtl = 0; mtl < nmt; mtl++) {
                int mt = wid + mtl*4;
                int row = mt*16 + ((lane >> 3) & 1) * 8 + (lane & 7);
                uint32_t addr = uQ + row*QSTR + kh*32 + (lane >> 4) * 16;
                uint32_t afr[4];
                LDMATRIX_X4(afr[0], afr[1], afr[2], afr[3], addr);
                #pragma unroll
                for (int nt = 0; nt < 14; nt++)
                    MMA_BF16(acc[mtl][nt], afr, bfr[nt]);
            }
        }
        for (int mtl = 0; mtl < nmt; mtl++) {
            int mt = wid + mtl*4;
            int r0 = mt*16 + (lane >> 2);
            int c0 = (lane & 3) * 2;
            #pragma unroll
            for (int nt = 0; nt < 14; nt++) {
                *(float2*)&S[r0*SSTR + nt*8 + c0]     = make_float2(acc[mtl][nt][0], acc[mtl][nt][1]);
                *(float2*)&S[(r0+8)*SSTR + nt*8 + c0] = make_float2(acc[mtl][nt][2], acc[mtl][nt][3]);
            }
        }
    }
    __syncthreads();

    // ---- softmax with bias + shift mask; P -> bf16 (scaled by 1/sum) ----
    if (tid < N_) {
        int r = tid;
        int regr = tc[r];
        const float* brow = g_bias + head*(N_*N_) + r*N_;
        float* srow = S + r*SSTR;
        float mx = -1e30f;
        for (int m = 0; m < N_; m++) {
            float s = srow[m] * 0.17677669529663687f + __ldg(&brow[m]);
            if (regr != tc[m]) s -= 100.0f;
            srow[m] = s;
            mx = fmaxf(mx, s);
        }
        float sum = 0.f;
        for (int m = 0; m < N_; m++) {
            float e = __expf(srow[m] - mx);
            srow[m] = e;
            sum += e;
        }
        float inv = 1.0f / sum;
        uint32_t* prow = (uint32_t*)(asmem + SM_P + r*PSTR);
        for (int m = 0; m < N_; m += 2)
            prow[m >> 1] = pack2(__float2bfloat16_rn(srow[m]*inv),
                                 __float2bfloat16_rn(srow[m+1]*inv));
        #pragma unroll
        for (int m = 49; m < 56; m++) prow[m] = 0;   // zero P cols 98..111
    }
    __syncthreads();

    // ---- AV: out[98][32] = P[98][112] @ V[112][32]  (7 k16, 4 n8) ----
    {
        float av[2][4][4] = {};
        #pragma unroll
        for (int kt = 0; kt < 7; kt++) {
            uint32_t vfr[4][2];
            #pragma unroll
            for (int np = 0; np < 2; np++) {
                int krow = kt*16 + ((lane >> 3) & 1) * 8 + (lane & 7);
                int ncol = np*16 + (lane >> 4) * 8;
                uint32_t addr = uV + krow*QSTR + ncol*2;
                uint32_t r0, r1, r2, r3;
                LDMATRIX_X4T(r0, r1, r2, r3, addr);
                vfr[np*2][0] = r0; vfr[np*2][1] = r1;
                vfr[np*2+1][0] = r2; vfr[np*2+1][1] = r3;
            }
            for (int mtl = 0; mtl < nmt; mtl++) {
                int mt = wid + mtl*4;
                int row = mt*16 + ((lane >> 3) & 1) * 8 + (lane & 7);
                uint32_t addr = uP + row*PSTR + kt*32 + (lane >> 4) * 16;
                uint32_t afr[4];
                LDMATRIX_X4(afr[0], afr[1], afr[2], afr[3], addr);
                #pragma unroll
                for (int nt = 0; nt < 4; nt++)
                    MMA_BF16(av[mtl][nt], afr, vfr[nt]);
            }
        }
        // store to g_att (2-seg)
        for (int mtl = 0; mtl < nmt; mtl++) {
            int mt = wid + mtl*4;
            int r0 = mt*16 + (lane >> 2);
            int cb = head*HD + (lane & 3) * 2;
            #pragma unroll
            for (int nt = 0; nt < 4; nt++) {
                if (r0 < N_)
                    split_store2(g_att + ((size_t)(bw*N_ + r0))*512, cb + nt*8,
                                 av[mtl][nt][0], av[mtl][nt][1]);
                if (r0 + 8 < N_)
                    split_store2(g_att + ((size_t)(bw*N_ + r0 + 8))*512, cb + nt*8,
                                 av[mtl][nt][2], av[mtl][nt][3]);
            }
        }
    }
}

// ---------------- host launcher ---------------------------------------------
extern "C" void kernel_launch(void* const* d_in, const int* in_sizes, int n_in,
                              void* d_out, int out_size) {
    const float* x     = (const float*)d_in[0];
    const float* n1w   = (const float*)d_in[1];
    const float* n1b   = (const float*)d_in[2];
    const float* qkvw  = (const float*)d_in[3];
    const float* qkvb  = (const float*)d_in[4];
    const float* projw = (const float*)d_in[5];
    const float* projb = (const float*)d_in[6];
    const float* rpe   = (const float*)d_in[7];
    const float* n2w   = (const float*)d_in[8];
    const float* n2b   = (const float*)d_in[9];
    const float* fc1w  = (const float*)d_in[10];
    const float* fc1b  = (const float*)d_in[11];
    const float* fc2w  = (const float*)d_in[12];
    const float* fc2b  = (const float*)d_in[13];
    float* out = (float*)d_out;

    __nv_bfloat16 *p_xw, *p_qkv, *p_att, *p_hn, *p_h3, *p_wqkv, *p_wproj, *p_wfc1, *p_wfc2;
    float *p_x2;
    cudaGetSymbolAddress((void**)&p_xw,  g_xw);
    cudaGetSymbolAddress((void**)&p_qkv, g_qkv);
    cudaGetSymbolAddress((void**)&p_att, g_att);
    cudaGetSymbolAddress((void**)&p_x2,  g_x2);
    cudaGetSymbolAddress((void**)&p_hn,  g_hn);
    cudaGetSymbolAddress((void**)&p_h3,  g_h3);
    cudaGetSymbolAddress((void**)&p_wqkv,  g_wqkv);
    cudaGetSymbolAddress((void**)&p_wproj, g_wproj);
    cudaGetSymbolAddress((void**)&p_wfc1,  g_wfc1);
    cudaGetSymbolAddress((void**)&p_wfc2,  g_wfc2);

    cudaFuncSetAttribute(attn_tc, cudaFuncAttributeMaxDynamicSharedMemorySize, ATTN_SMEM);
    cudaFuncSetAttribute(gemm_mma<0>, cudaFuncAttributeMaxDynamicSharedMemorySize, GEMM_SMEM);
    cudaFuncSetAttribute(gemm_mma<1>, cudaFuncAttributeMaxDynamicSharedMemorySize, GEMM_SMEM);
    cudaFuncSetAttribute(gemm_mma<2>, cudaFuncAttributeMaxDynamicSharedMemorySize, GEMM_SMEM);
    cudaFuncSetAttribute(gemm_mma<3>, cudaFuncAttributeMaxDynamicSharedMemorySize, GEMM_SMEM);

    // setup (independent of activations)
    convert_w<<<(768*256 + 255)/256, 256>>>(qkvw,  p_wqkv, 768, 256, 2);
    convert_w<<<(256*256 + 255)/256, 256>>>(projw, p_wproj, 256, 256, 2);
    convert_w<<<(1024*256 + 255)/256, 256>>>(fc1w, p_wfc1, 1024, 256, 1);
    convert_w<<<(256*1024 + 255)/256, 256>>>(fc2w, p_wfc2, 256, 1024, 1);
    build_bias<<<(N_*N_ + 127)/128, 128>>>(rpe);

    // 1. LN1 + roll + window partition -> 2-seg bf16
    ln_kernel<<<NTOK/8, 256>>>(x, p_xw, n1w, n1b, 0);
    // 2. QKV GEMM (2-seg, K3=512) -> plain bf16
    gemm_mma<0><<<dim3(6, 392), 256, GEMM_SMEM>>>(p_xw, p_wqkv, qkvb, nullptr, nullptr, p_qkv, 512);
    // 3. tensor-core windowed attention
    attn_tc<<<BW_*HEADS, 128, ATTN_SMEM>>>();
    // 4. proj GEMM (2-seg) + reverse/roll + residual
    gemm_mma<2><<<dim3(2, 392), 256, GEMM_SMEM>>>(p_att, p_wproj, projb, x, p_x2, nullptr, 512);
    // 5. LN2 -> plain bf16
    ln_kernel<<<NTOK/8, 256>>>(p_x2, p_hn, n2w, n2b, 1);
    // 6. fc1 GEMM + GELU -> plain bf16
    gemm_mma<1><<<dim3(8, 392), 256, GEMM_SMEM>>>(p_hn, p_wfc1, fc1b, nullptr, nullptr, p_h3, 256);
    // 7. fc2 GEMM + residual -> out
    gemm_mma<3><<<dim3(2, 392), 256, GEMM_SMEM>>>(p_h3, p_wfc2, fc2b, p_x2, out, nullptr, 1024);
}

// round 7
// speedup vs baseline: 4.9781x; 1.1378x over previous
#include <cuda_runtime.h>
#include <cuda_bf16.h>
#include <math.h>
#include <stdint.h>

// ---------------- problem constants ----------------
#define DIM   256
#define HEADS 8
#define HD    32
#define B_    2
#define T_    8
#define H_    56
#define W_    56
#define WT    2
#define WH    7
#define WW    7
#define STs   1
#define SHs   3
#define SWs   3
#define NTOK  (B_*T_*H_*W_)   // 50176 = 392*128
#define BW_   512
#define N_    98
#define HID   1024

// ---------------- scratch (device globals) ----------
__device__ __nv_bfloat16 g_xw [NTOK*256];          // LN1 bf16, window layout
__device__ __nv_bfloat16 g_qkv[(size_t)NTOK*768];  // qkv bf16
__device__ __nv_bfloat16 g_att[NTOK*256];          // attn out bf16
__device__ float         g_x2 [NTOK*256];          // residual-1
__device__ __nv_bfloat16 g_hn [NTOK*256];          // LN2 bf16
__device__ __nv_bfloat16 g_h3 [(size_t)NTOK*1024]; // fc1+gelu bf16
__device__ __nv_bfloat16 g_wqkv [768*256];
__device__ __nv_bfloat16 g_wproj[256*256];
__device__ __nv_bfloat16 g_wfc1 [1024*256];
__device__ __nv_bfloat16 g_wfc2 [256*1024];
__device__ float         g_bias[HEADS*N_*N_];      // precomputed rpe bias

// ---------------- PTX helpers ----------------------
__device__ __forceinline__ uint32_t smem_u32(const void* p) {
    uint32_t a;
    asm("{ .reg .u64 t; cvta.to.shared.u64 t, %1; cvt.u32.u64 %0, t; }" : "=r"(a) : "l"(p));
    return a;
}
#define CP_ASYNC16(sm, gp) \
    asm volatile("cp.async.cg.shared.global [%0], [%1], 16;" :: "r"(sm), "l"(gp))
#define CP_COMMIT() asm volatile("cp.async.commit_group;" ::: "memory")
#define CP_WAIT0()  asm volatile("cp.async.wait_group 0;" ::: "memory")
#define CP_WAIT1()  asm volatile("cp.async.wait_group 1;" ::: "memory")

#define LDMATRIX_X4(r0,r1,r2,r3,addr) \
    asm volatile("ldmatrix.sync.aligned.m8n8.x4.shared.b16 {%0,%1,%2,%3}, [%4];" \
        : "=r"(r0), "=r"(r1), "=r"(r2), "=r"(r3) : "r"(addr))
#define LDMATRIX_X4T(r0,r1,r2,r3,addr) \
    asm volatile("ldmatrix.sync.aligned.m8n8.x4.trans.shared.b16 {%0,%1,%2,%3}, [%4];" \
        : "=r"(r0), "=r"(r1), "=r"(r2), "=r"(r3) : "r"(addr))
#define MMA_BF16(c, a, b) \
    asm volatile("mma.sync.aligned.m16n8k16.row.col.f32.bf16.bf16.f32 " \
        "{%0,%1,%2,%3}, {%4,%5,%6,%7}, {%8,%9}, {%0,%1,%2,%3};" \
        : "+f"((c)[0]), "+f"((c)[1]), "+f"((c)[2]), "+f"((c)[3]) \
        : "r"((a)[0]), "r"((a)[1]), "r"((a)[2]), "r"((a)[3]), "r"((b)[0]), "r"((b)[1]))

// ---------------- bf16 store helpers ----------------
__device__ __forceinline__ uint32_t pack2(__nv_bfloat16 a, __nv_bfloat16 b) {
    return (uint32_t)__bfloat16_as_ushort(a) | ((uint32_t)__bfloat16_as_ushort(b) << 16);
}
__device__ __forceinline__ void plain_store4(__nv_bfloat16* rowp, int col,
                                             float a0, float a1, float a2, float a3) {
    uint2 u;
    u.x = pack2(__float2bfloat16_rn(a0), __float2bfloat16_rn(a1));
    u.y = pack2(__float2bfloat16_rn(a2), __float2bfloat16_rn(a3));
    *(uint2*)(rowp + col) = u;
}

// ---------------- fused setup: all weight converts + rpe bias table --------
#define NW_QKV (768*256)
#define NW_PROJ (256*256)
#define NW_FC1 (1024*256)
#define NW_FC2 (256*1024)
#define SETUP_ITEMS (NW_QKV + NW_PROJ + NW_FC1 + NW_FC2 + N_*N_)

__global__ void setup_kernel(const float* __restrict__ qkvw, const float* __restrict__ projw,
                             const float* __restrict__ fc1w, const float* __restrict__ fc2w,
                             const float* __restrict__ rpe) {
    int idx = blockIdx.x * 256 + threadIdx.x;
    if (idx >= SETUP_ITEMS) return;
    if (idx < NW_QKV) {
        g_wqkv[idx] = __float2bfloat16_rn(qkvw[idx]);
    } else if ((idx -= NW_QKV) < NW_PROJ) {
        g_wproj[idx] = __float2bfloat16_rn(projw[idx]);
    } else if ((idx -= NW_PROJ) < NW_FC1) {
        g_wfc1[idx] = __float2bfloat16_rn(fc1w[idx]);
    } else if ((idx -= NW_FC1) < NW_FC2) {
        g_wfc2[idx] = __float2bfloat16_rn(fc2w[idx]);
    } else {
        int i = idx - NW_FC2;
        int r = i / N_, m = i % N_;
        int tr = r / 49, hr = (r % 49) / 7, wr = r % 7;
        int tm = m / 49, hm = (m % 49) / 7, wm = m % 7;
        int t = (tr - tm + (WT-1)) * ((2*WH-1)*(2*WW-1))
              + (hr - hm + (WH-1)) * (2*WW-1)
              + (wr - wm + (WW-1));
        #pragma unroll
        for (int h = 0; h < HEADS; h++)
            g_bias[h*N_*N_ + i] = rpe[t*HEADS + h];
    }
}

// ---------------- LN kernel (mode 0: +roll+partition; mode 1: plain) -------
__global__ void ln_kernel(const float* __restrict__ src, __nv_bfloat16* __restrict__ dst,
                          const float* __restrict__ w, const float* __restrict__ b, int mode) {
    int warp = threadIdx.x >> 5, lane = threadIdx.x & 31;
    int row = blockIdx.x * 8 + warp;
    const float* sr = src + (size_t)row * DIM;
    float4 v0 = *(const float4*)(sr + lane * 4);
    float4 v1 = *(const float4*)(sr + 128 + lane * 4);
    float s  = v0.x + v0.y + v0.z + v0.w + v1.x + v1.y + v1.z + v1.w;
    float ss = v0.x*v0.x + v0.y*v0.y + v0.z*v0.z + v0.w*v0.w
             + v1.x*v1.x + v1.y*v1.y + v1.z*v1.z + v1.w*v1.w;
    #pragma unroll
    for (int o = 16; o > 0; o >>= 1) {
        s  += __shfl_xor_sync(0xffffffffu, s, o);
        ss += __shfl_xor_sync(0xffffffffu, ss, o);
    }
    float mean = s * (1.0f / 256.0f);
    float var  = ss * (1.0f / 256.0f) - mean * mean;
    float inv  = rsqrtf(var + 1e-5f);
    int c0 = lane * 4, c1 = 128 + lane * 4;
    float o00 = (v0.x - mean) * inv * w[c0+0] + b[c0+0];
    float o01 = (v0.y - mean) * inv * w[c0+1] + b[c0+1];
    float o02 = (v0.z - mean) * inv * w[c0+2] + b[c0+2];
    float o03 = (v0.w - mean) * inv * w[c0+3] + b[c0+3];
    float o10 = (v1.x - mean) * inv * w[c1+0] + b[c1+0];
    float o11 = (v1.y - mean) * inv * w[c1+1] + b[c1+1];
    float o12 = (v1.z - mean) * inv * w[c1+2] + b[c1+2];
    float o13 = (v1.w - mean) * inv * w[c1+3] + b[c1+3];

    size_t drow = row;
    if (mode == 0) {
        int bb = row / (T_*H_*W_);
        int r2 = row % (T_*H_*W_);
        int t = r2 / (H_*W_);
        int r3 = r2 % (H_*W_);
        int h = r3 / W_, ww_ = r3 % W_;
        int t2 = t - STs; if (t2 < 0) t2 += T_;
        int h2 = h - SHs; if (h2 < 0) h2 += H_;
        int w2 = ww_ - SWs; if (w2 < 0) w2 += W_;
        int tw = t2 / WT, hw = h2 / WH, wwn = w2 / WW;
        int n = (t2 % WT) * 49 + (h2 % WH) * 7 + (w2 % WW);
        int bw = ((bb * 4 + tw) * 8 + hw) * 8 + wwn;
        drow = (size_t)bw * N_ + n;
    }
    __nv_bfloat16* dr = dst + drow * 256;
    plain_store4(dr, c0, o00, o01, o02, o03);
    plain_store4(dr, c1, o10, o11, o12, o13);
}

// ---------------- mma.sync GEMM ----------------------------
// EPI 0: +bias -> bf16 stride 768 (qkv)
// EPI 1: +bias,GELU -> bf16 stride 1024 (fc1)
// EPI 2: +bias, reverse+roll remap, +resid -> fp32 (proj)
// EPI 3: +bias, +resid -> fp32 (fc2)
#define ABUF 18432
#define BUFSZ (2*ABUF)
#define GEMM_SMEM (3*BUFSZ)

template<int EPI>
__global__ __launch_bounds__(256) void gemm_mma(
        const __nv_bfloat16* __restrict__ A, const __nv_bfloat16* __restrict__ Wm,
        const float* __restrict__ bias, const float* __restrict__ resid,
        float* __restrict__ outF, __nv_bfloat16* __restrict__ outB, int K3) {
    extern __shared__ __align__(16) char smraw[];
    int tid = threadIdx.x, lane = tid & 31, wid = tid >> 5;
    int brow = blockIdx.y * 128, bcol = blockIdx.x * 128;
    int wm = wid & 1, wn = wid >> 1;
    uint32_t sb = smem_u32(smraw);

    float acc[4][4][4] = {};
    const int NC = K3 >> 6;

    const char* Agc = (const char*)(A  + (size_t)brow * K3);
    const char* Bgc = (const char*)(Wm + (size_t)bcol * K3);
    size_t rowstride = (size_t)K3 * 2;

    auto loadChunk = [&](int c, int buf) {
        uint32_t abase = sb + buf * BUFSZ;
        uint32_t bbase = abase + ABUF;
        const char* Ag = Agc + (size_t)c * 128;
        const char* Bg = Bgc + (size_t)c * 128;
        #pragma unroll
        for (int j = 0; j < 4; j++) {
            int x = tid + j * 256;
            int row = x >> 3, kc = x & 7;
            CP_ASYNC16(abase + row * 144 + kc * 16, Ag + (size_t)row * rowstride + kc * 16);
            CP_ASYNC16(bbase + row * 144 + kc * 16, Bg + (size_t)row * rowstride + kc * 16);
        }
        CP_COMMIT();
    };

    loadChunk(0, 0);
    if (NC > 1) loadChunk(1, 1);
    int bc = 0, bn2 = 2;
    for (int c = 0; c < NC; c++) {
        if (c + 1 < NC) CP_WAIT1(); else CP_WAIT0();
        __syncthreads();
        if (c + 2 < NC) loadChunk(c + 2, bn2);
        uint32_t abase = sb + bc * BUFSZ;
        uint32_t bbase = abase + ABUF;
        #pragma unroll
        for (int kh = 0; kh < 4; kh++) {
            uint32_t afr[4][4];
            #pragma unroll
            for (int mt = 0; mt < 4; mt++) {
                int row = wm * 64 + mt * 16 + ((lane >> 3) & 1) * 8 + (lane & 7);
                uint32_t addr = abase + row * 144 + kh * 32 + (lane >> 4) * 16;
                LDMATRIX_X4(afr[mt][0], afr[mt][1], afr[mt][2], afr[mt][3], addr);
            }
            uint32_t bfr[4][2];
            #pragma unroll
            for (int np = 0; np < 2; np++) {
                int nrow = wn * 32 + np * 16 + (lane >> 4) * 8 + (lane & 7);
                uint32_t addr = bbase + nrow * 144 + kh * 32 + ((lane >> 3) & 1) * 16;
                uint32_t r0, r1, r2, r3;
                LDMATRIX_X4(r0, r1, r2, r3, addr);
                bfr[np*2][0] = r0; bfr[np*2][1] = r1;
                bfr[np*2+1][0] = r2; bfr[np*2+1][1] = r3;
            }
            #pragma unroll
            for (int mt = 0; mt < 4; mt++)
                #pragma unroll
                for (int nt = 0; nt < 4; nt++)
                    MMA_BF16(acc[mt][nt], afr[mt], bfr[nt]);
        }
        bc++;  if (bc == 3)  bc = 0;
        bn2++; if (bn2 == 3) bn2 = 0;
    }
    __syncthreads();

    float* Cs = (float*)smraw;
    #pragma unroll
    for (int mt = 0; mt < 4; mt++)
        #pragma unroll
        for (int nt = 0; nt < 4; nt++) {
            int r0 = wm * 64 + mt * 16 + (lane >> 2);
            int cc = wn * 32 + nt * 8 + (lane & 3) * 2;
            Cs[r0 * 132 + cc]       = acc[mt][nt][0];
            Cs[r0 * 132 + cc + 1]   = acc[mt][nt][1];
            Cs[(r0+8) * 132 + cc]   = acc[mt][nt][2];
            Cs[(r0+8) * 132 + cc+1] = acc[mt][nt][3];
        }
    __syncthreads();

    float4 bs = *(const float4*)(bias + bcol + lane * 4);
    for (int r = wid; r < 128; r += 8) {
        float4 v = *(const float4*)&Cs[r * 132 + lane * 4];
        v.x += bs.x; v.y += bs.y; v.z += bs.z; v.w += bs.w;
        int grow = brow + r;
        int col = bcol + lane * 4;
        if (EPI == 0) {
            plain_store4(outB + (size_t)grow * 768, col, v.x, v.y, v.z, v.w);
        } else if (EPI == 1) {
            float g0 = 0.5f * v.x * (1.0f + erff(v.x * 0.70710678118654752f));
            float g1 = 0.5f * v.y * (1.0f + erff(v.y * 0.70710678118654752f));
            float g2 = 0.5f * v.z * (1.0f + erff(v.z * 0.70710678118654752f));
            float g3 = 0.5f * v.w * (1.0f + erff(v.w * 0.70710678118654752f));
            plain_store4(outB + (size_t)grow * 1024, col, g0, g1, g2, g3);
        } else if (EPI == 2) {
            int bw = grow / N_, n = grow % N_;
            int bb = bw >> 8, wrem = bw & 255;
            int tw = wrem >> 6, hw = (wrem >> 3) & 7, wwn = wrem & 7;
            int nt = n / 49, nr = n % 49;
            int t2 = tw*WT + nt, h2 = hw*WH + nr/7, w2 = wwn*WW + nr%7;
            int t = t2 + STs; if (t >= T_) t -= T_;
            int h = h2 + SHs; if (h >= H_) h -= H_;
            int ww_ = w2 + SWs; if (ww_ >= W_) ww_ -= W_;
            size_t orow = ((size_t)((bb*T_ + t)*H_ + h))*W_ + ww_;
            float4 rr = *(const float4*)(resid + orow * 256 + col);
            v.x += rr.x; v.y += rr.y; v.z += rr.z; v.w += rr.w;
            *(float4*)(outF + orow * 256 + col) = v;
        } else {
            float4 rr = *(const float4*)(resid + (size_t)grow * 256 + col);
            v.x += rr.x; v.y += rr.y; v.z += rr.z; v.w += rr.w;
            *(float4*)(outF + (size_t)grow * 256 + col) = v;
        }
    }
}

// ---------------- tensor-core attention ---------------------
#define QSTR 80
#define PSTR 240
#define SSTR 114
#define SM_Q  0
#define SM_K  (112*QSTR)
#define SM_V  (2*112*QSTR)
#define SM_P  (3*112*QSTR)
#define SM_S  (SM_P + 112*PSTR)
#define SM_TC (SM_S + 112*SSTR*4)
#define ATTN_SMEM (SM_TC + 112*4)

__global__ __launch_bounds__(128) void attn_tc() {
    extern __shared__ __align__(16) char asmem[];
    float* S = (float*)(asmem + SM_S);
    int* tc  = (int*)(asmem + SM_TC);

    int tid = threadIdx.x, lane = tid & 31, wid = tid >> 5;
    int head = blockIdx.x & 7, bw = blockIdx.x >> 3;
    int wrem = bw & 255;
    int tw = wrem >> 6, hw = (wrem >> 3) & 7, wwn = wrem & 7;

    uint32_t uQ = smem_u32(asmem + SM_Q);
    uint32_t uK = smem_u32(asmem + SM_K);
    uint32_t uV = smem_u32(asmem + SM_V);
    uint32_t uP = smem_u32(asmem + SM_P);

    if (tid < N_) {
        const uint4* g = (const uint4*)(g_qkv + ((size_t)(bw*N_ + tid)) * 768 + head * HD);
        #pragma unroll
        for (int j = 0; j < 4; j++) {
            *(uint4*)(asmem + SM_Q + tid*QSTR + j*16) = g[j];
            *(uint4*)(asmem + SM_K + tid*QSTR + j*16) = g[32 + j];
            *(uint4*)(asmem + SM_V + tid*QSTR + j*16) = g[64 + j];
        }
        int t = tid / 49, rem = tid % 49, h = rem / 7, w = rem % 7;
        int gt = tw*WT + t, gh = hw*WH + h, gw = wwn*WW + w;
        int rt = (gt < T_-WT) ? 0 : ((gt < T_-STs) ? 1 : 2);
        int rh = (gh < H_-WH) ? 0 : ((gh < H_-SHs) ? 1 : 2);
        int rw = (gw < W_-WW) ? 0 : ((gw < W_-SWs) ? 1 : 2);
        tc[tid] = rt*9 + rh*3 + rw;
    } else if (tid < 112) {
        uint4 z = make_uint4(0,0,0,0);
        #pragma unroll
        for (int j = 0; j < 4; j++)
            *(uint4*)(asmem + SM_V + tid*QSTR + j*16) = z;
    }
    __syncthreads();

    int nmt = (wid < 3) ? 2 : 1;

    // ---- QK^T ----
    {
        float acc[2][14][4] = {};
        #pragma unroll
        for (int kh = 0; kh < 2; kh++) {
            uint32_t bfr[14][2];
            #pragma unroll
            for (int np = 0; np < 7; np++) {
                int nrow = np*16 + (lane >> 4) * 8 + (lane & 7);
                uint32_t addr = uK + nrow*QSTR + kh*32 + ((lane >> 3) & 1) * 16;
                uint32_t r0, r1, r2, r3;
                LDMATRIX_X4(r0, r1, r2, r3, addr);
                bfr[np*2][0] = r0; bfr[np*2][1] = r1;
                bfr[np*2+1][0] = r2; bfr[np*2+1][1] = r3;
            }
            for (int mtl = 0; mtl < nmt; mtl++) {
                int mt = wid + mtl*4;
                int row = mt*16 + ((lane >> 3) & 1) * 8 + (lane & 7);
                uint32_t addr = uQ + row*QSTR + kh*32 + (lane >> 4) * 16;
                uint32_t afr[4];
                LDMATRIX_X4(afr[0], afr[1], afr[2], afr[3], addr);
                #pragma unroll
                for (int nt = 0; nt < 14; nt++)
                    MMA_BF16(acc[mtl][nt], afr, bfr[nt]);
            }
        }
        for (int mtl = 0; mtl < nmt; mtl++) {
            int mt = wid + mtl*4;
            int r0 = mt*16 + (lane >> 2);
            int c0 = (lane & 3) * 2;
            #pragma unroll
            for (int nt = 0; nt < 14; nt++) {
                *(float2*)&S[r0*SSTR + nt*8 + c0]     = make_float2(acc[mtl][nt][0], acc[mtl][nt][1]);
                *(float2*)&S[(r0+8)*SSTR + nt*8 + c0] = make_float2(acc[mtl][nt][2], acc[mtl][nt][3]);
            }
        }
    }
    __syncthreads();

    // ---- softmax ----
    if (tid < N_) {
        int r = tid;
        int regr = tc[r];
        const float* brow = g_bias + head*(N_*N_) + r*N_;
        float* srow = S + r*SSTR;
        float mx = -1e30f;
        for (int m = 0; m < N_; m++) {
            float s = srow[m] * 0.17677669529663687f + __ldg(&brow[m]);
            if (regr != tc[m]) s -= 100.0f;
            srow[m] = s;
            mx = fmaxf(mx, s);
        }
        float sum = 0.f;
        for (int m = 0; m < N_; m++) {
            float e = __expf(srow[m] - mx);
            srow[m] = e;
            sum += e;
        }
        float inv = 1.0f / sum;
        uint32_t* prow = (uint32_t*)(asmem + SM_P + r*PSTR);
        for (int m = 0; m < N_; m += 2)
            prow[m >> 1] = pack2(__float2bfloat16_rn(srow[m]*inv),
                                 __float2bfloat16_rn(srow[m+1]*inv));
        #pragma unroll
        for (int m = 49; m < 56; m++) prow[m] = 0;
    }
    __syncthreads();

    // ---- AV ----
    {
        float av[2][4][4] = {};
        #pragma unroll
        for (int kt = 0; kt < 7; kt++) {
            uint32_t vfr[4][2];
            #pragma unroll
            for (int np = 0; np < 2; np++) {
                int krow = kt*16 + ((lane >> 3) & 1) * 8 + (lane & 7);
                int ncol = np*16 + (lane >> 4) * 8;
                uint32_t addr = uV + krow*QSTR + ncol*2;
                uint32_t r0, r1, r2, r3;
                LDMATRIX_X4T(r0, r1, r2, r3, addr);
                vfr[np*2][0] = r0; vfr[np*2][1] = r1;
                vfr[np*2+1][0] = r2; vfr[np*2+1][1] = r3;
            }
            for (int mtl = 0; mtl < nmt; mtl++) {
                int mt = wid + mtl*4;
                int row = mt*16 + ((lane >> 3) & 1) * 8 + (lane & 7);
                uint32_t addr = uP + row*PSTR + kt*32 + (lane >> 4) * 16;
                uint32_t afr[4];
                LDMATRIX_X4(afr[0], afr[1], afr[2], afr[3], addr);
                #pragma unroll
                for (int nt = 0; nt < 4; nt++)
                    MMA_BF16(av[mtl][nt], afr, vfr[nt]);
            }
        }
        for (int mtl = 0; mtl < nmt; mtl++) {
            int mt = wid + mtl*4;
            int r0 = mt*16 + (lane >> 2);
            int cb = head*HD + (lane & 3) * 2;
            #pragma unroll
            for (int nt = 0; nt < 4; nt++) {
                if (r0 < N_)
                    *(uint32_t*)(g_att + ((size_t)(bw*N_ + r0))*256 + cb + nt*8)
                        = pack2(__float2bfloat16_rn(av[mtl][nt][0]), __float2bfloat16_rn(av[mtl][nt][1]));
                if (r0 + 8 < N_)
                    *(uint32_t*)(g_att + ((size_t)(bw*N_ + r0 + 8))*256 + cb + nt*8)
                        = pack2(__float2bfloat16_rn(av[mtl][nt][2]), __float2bfloat16_rn(av[mtl][nt][3]));
            }
        }
    }
}

// ---------------- host launcher ---------------------------------------------
extern "C" void kernel_launch(void* const* d_in, const int* in_sizes, int n_in,
                              void* d_out, int out_size) {
    const float* x     = (const float*)d_in[0];
    const float* n1w   = (const float*)d_in[1];
    const float* n1b   = (const float*)d_in[2];
    const float* qkvw  = (const float*)d_in[3];
    const float* qkvb  = (const float*)d_in[4];
    const float* projw = (const float*)d_in[5];
    const float* projb = (const float*)d_in[6];
    const float* rpe   = (const float*)d_in[7];
    const float* n2w   = (const float*)d_in[8];
    const float* n2b   = (const float*)d_in[9];
    const float* fc1w  = (const float*)d_in[10];
    const float* fc1b  = (const float*)d_in[11];
    const float* fc2w  = (const float*)d_in[12];
    const float* fc2b  = (const float*)d_in[13];
    float* out = (float*)d_out;

    __nv_bfloat16 *p_xw, *p_qkv, *p_att, *p_hn, *p_h3, *p_wqkv, *p_wproj, *p_wfc1, *p_wfc2;
    float *p_x2;
    cudaGetSymbolAddress((void**)&p_xw,  g_xw);
    cudaGetSymbolAddress((void**)&p_qkv, g_qkv);
    cudaGetSymbolAddress((void**)&p_att, g_att);
    cudaGetSymbolAddress((void**)&p_x2,  g_x2);
    cudaGetSymbolAddress((void**)&p_hn,  g_hn);
    cudaGetSymbolAddress((void**)&p_h3,  g_h3);
    cudaGetSymbolAddress((void**)&p_wqkv,  g_wqkv);
    cudaGetSymbolAddress((void**)&p_wproj, g_wproj);
    cudaGetSymbolAddress((void**)&p_wfc1,  g_wfc1);
    cudaGetSymbolAddress((void**)&p_wfc2,  g_wfc2);

    cudaFuncSetAttribute(attn_tc, cudaFuncAttributeMaxDynamicSharedMemorySize, ATTN_SMEM);
    cudaFuncSetAttribute(gemm_mma<0>, cudaFuncAttributeMaxDynamicSharedMemorySize, GEMM_SMEM);
    cudaFuncSetAttribute(gemm_mma<1>, cudaFuncAttributeMaxDynamicSharedMemorySize, GEMM_SMEM);
    cudaFuncSetAttribute(gemm_mma<2>, cudaFuncAttributeMaxDynamicSharedMemorySize, GEMM_SMEM);
    cudaFuncSetAttribute(gemm_mma<3>, cudaFuncAttributeMaxDynamicSharedMemorySize, GEMM_SMEM);

    // fused setup (weights + bias table)
    setup_kernel<<<(SETUP_ITEMS + 255)/256, 256>>>(qkvw, projw, fc1w, fc2w, rpe);

    // 1. LN1 + roll + window partition -> bf16
    ln_kernel<<<NTOK/8, 256>>>(x, p_xw, n1w, n1b, 0);
    // 2. QKV GEMM (K=256) -> bf16
    gemm_mma<0><<<dim3(6, 392), 256, GEMM_SMEM>>>(p_xw, p_wqkv, qkvb, nullptr, nullptr, p_qkv, 256);
    // 3. tensor-core windowed attention
    attn_tc<<<BW_*HEADS, 128, ATTN_SMEM>>>();
    // 4. proj GEMM (K=256) + reverse/roll + residual
    gemm_mma<2><<<dim3(2, 392), 256, GEMM_SMEM>>>(p_att, p_wproj, projb, x, p_x2, nullptr, 256);
    // 5. LN2 -> bf16
    ln_kernel<<<NTOK/8, 256>>>(p_x2, p_hn, n2w, n2b, 1);
    // 6. fc1 GEMM (K=256) + GELU -> bf16
    gemm_mma<1><<<dim3(8, 392), 256, GEMM_SMEM>>>(p_hn, p_wfc1, fc1b, nullptr, nullptr, p_h3, 256);
    // 7. fc2 GEMM (K=1024) + residual -> out
    gemm_mma<3><<<dim3(2, 392), 256, GEMM_SMEM>>>(p_h3, p_wfc2, fc2b, p_x2, out, nullptr, 1024);
}

// round 8
// speedup vs baseline: 6.4441x; 1.2945x over previous
#include <cuda_runtime.h>
#include <cuda_bf16.h>
#include <math.h>
#include <stdint.h>

// ---------------- problem constants ----------------
#define DIM   256
#define HEADS 8
#define HD    32
#define B_    2
#define T_    8
#define H_    56
#define W_    56
#define WT    2
#define WH    7
#define WW    7
#define STs   1
#define SHs   3
#define SWs   3
#define NTOK  (B_*T_*H_*W_)   // 50176 = 392*128
#define BW_   512
#define N_    98
#define HID   1024

// ---------------- scratch (device globals) ----------
__device__ __nv_bfloat16 g_xw [NTOK*256];
__device__ __nv_bfloat16 g_qkv[(size_t)NTOK*768];
__device__ __nv_bfloat16 g_att[NTOK*256];
__device__ float         g_x2 [NTOK*256];
__device__ __nv_bfloat16 g_hn [NTOK*256];
__device__ __nv_bfloat16 g_h3 [(size_t)NTOK*1024];
__device__ __nv_bfloat16 g_wqkv [768*256];
__device__ __nv_bfloat16 g_wproj[256*256];
__device__ __nv_bfloat16 g_wfc1 [1024*256];
__device__ __nv_bfloat16 g_wfc2 [256*1024];
__device__ float         g_bm[8*HEADS*112*112];   // bias + mask + col-pad, per window category

// ---------------- PTX helpers ----------------------
__device__ __forceinline__ uint32_t smem_u32(const void* p) {
    uint32_t a;
    asm("{ .reg .u64 t; cvta.to.shared.u64 t, %1; cvt.u32.u64 %0, t; }" : "=r"(a) : "l"(p));
    return a;
}
#define CP_ASYNC16(sm, gp) \
    asm volatile("cp.async.cg.shared.global [%0], [%1], 16;" :: "r"(sm), "l"(gp))
#define CP_COMMIT() asm volatile("cp.async.commit_group;" ::: "memory")
#define CP_WAIT0()  asm volatile("cp.async.wait_group 0;" ::: "memory")
#define CP_WAIT1()  asm volatile("cp.async.wait_group 1;" ::: "memory")

#define LDMATRIX_X4(r0,r1,r2,r3,addr) \
    asm volatile("ldmatrix.sync.aligned.m8n8.x4.shared.b16 {%0,%1,%2,%3}, [%4];" \
        : "=r"(r0), "=r"(r1), "=r"(r2), "=r"(r3) : "r"(addr))
#define LDMATRIX_X4T(r0,r1,r2,r3,addr) \
    asm volatile("ldmatrix.sync.aligned.m8n8.x4.trans.shared.b16 {%0,%1,%2,%3}, [%4];" \
        : "=r"(r0), "=r"(r1), "=r"(r2), "=r"(r3) : "r"(addr))
#define MMA_BF16(c, a, b) \
    asm volatile("mma.sync.aligned.m16n8k16.row.col.f32.bf16.bf16.f32 " \
        "{%0,%1,%2,%3}, {%4,%5,%6,%7}, {%8,%9}, {%0,%1,%2,%3};" \
        : "+f"((c)[0]), "+f"((c)[1]), "+f"((c)[2]), "+f"((c)[3]) \
        : "r"((a)[0]), "r"((a)[1]), "r"((a)[2]), "r"((a)[3]), "r"((b)[0]), "r"((b)[1]))

// ---------------- bf16 store helpers ----------------
__device__ __forceinline__ uint32_t pack2(__nv_bfloat16 a, __nv_bfloat16 b) {
    return (uint32_t)__bfloat16_as_ushort(a) | ((uint32_t)__bfloat16_as_ushort(b) << 16);
}
__device__ __forceinline__ uint32_t pack2f(float a, float b) {
    return pack2(__float2bfloat16_rn(a), __float2bfloat16_rn(b));
}
__device__ __forceinline__ void plain_store4(__nv_bfloat16* rowp, int col,
                                             float a0, float a1, float a2, float a3) {
    uint2 u;
    u.x = pack2f(a0, a1);
    u.y = pack2f(a2, a3);
    *(uint2*)(rowp + col) = u;
}

// ---------------- fused setup: weight converts + bias/mask table -----------
#define NW_QKV (768*256)
#define NW_PROJ (256*256)
#define NW_FC1 (1024*256)
#define NW_FC2 (256*1024)
#define NBM    (8*112*112)
#define SETUP_ITEMS (NW_QKV + NW_PROJ + NW_FC1 + NW_FC2 + NBM)

__global__ void setup_kernel(const float* __restrict__ qkvw, const float* __restrict__ projw,
                             const float* __restrict__ fc1w, const float* __restrict__ fc2w,
                             const float* __restrict__ rpe) {
    int idx = blockIdx.x * 256 + threadIdx.x;
    if (idx >= SETUP_ITEMS) return;
    if (idx < NW_QKV) {
        g_wqkv[idx] = __float2bfloat16_rn(qkvw[idx]);
    } else if ((idx -= NW_QKV) < NW_PROJ) {
        g_wproj[idx] = __float2bfloat16_rn(projw[idx]);
    } else if ((idx -= NW_PROJ) < NW_FC1) {
        g_wfc1[idx] = __float2bfloat16_rn(fc1w[idx]);
    } else if ((idx -= NW_FC1) < NW_FC2) {
        g_wfc2[idx] = __float2bfloat16_rn(fc2w[idx]);
    } else {
        int i = idx - NW_FC2;          // < 8*112*112
        int cat = i / (112*112);
        int rm = i % (112*112);
        int r = rm / 112, m = rm % 112;
        if (r < N_ && m < N_) {
            int ct = cat >> 2, ch = (cat >> 1) & 1, cw = cat & 1;
            int tr = r/49, hr = (r%49)/7, wr = r%7;
            int tm = m/49, hm = (m%49)/7, wm = m%7;
            int regr = (ct ? (tr==0?1:2) : 0)*9 + (ch ? (hr<4?1:2) : 0)*3 + (cw ? (wr<4?1:2) : 0);
            int regm = (ct ? (tm==0?1:2) : 0)*9 + (ch ? (hm<4?1:2) : 0)*3 + (cw ? (wm<4?1:2) : 0);
            int tix = (tr - tm + 1)*169 + (hr - hm + 6)*13 + (wr - wm + 6);
            float msk = (regr != regm) ? -100.0f : 0.0f;
            #pragma unroll
            for (int h = 0; h < HEADS; h++)
                g_bm[((cat*8 + h)*112 + r)*112 + m] = rpe[tix*HEADS + h] + msk;
        } else {
            float v = (m >= N_) ? -1e30f : 0.0f;
            #pragma unroll
            for (int h = 0; h < HEADS; h++)
                g_bm[((cat*8 + h)*112 + r)*112 + m] = v;
        }
    }
}

// ---------------- LN kernel (mode 0: +roll+partition; mode 1: plain) -------
__global__ void ln_kernel(const float* __restrict__ src, __nv_bfloat16* __restrict__ dst,
                          const float* __restrict__ w, const float* __restrict__ b, int mode) {
    int warp = threadIdx.x >> 5, lane = threadIdx.x & 31;
    int row = blockIdx.x * 8 + warp;
    const float* sr = src + (size_t)row * DIM;
    float4 v0 = *(const float4*)(sr + lane * 4);
    float4 v1 = *(const float4*)(sr + 128 + lane * 4);
    float s  = v0.x + v0.y + v0.z + v0.w + v1.x + v1.y + v1.z + v1.w;
    float ss = v0.x*v0.x + v0.y*v0.y + v0.z*v0.z + v0.w*v0.w
             + v1.x*v1.x + v1.y*v1.y + v1.z*v1.z + v1.w*v1.w;
    #pragma unroll
    for (int o = 16; o > 0; o >>= 1) {
        s  += __shfl_xor_sync(0xffffffffu, s, o);
        ss += __shfl_xor_sync(0xffffffffu, ss, o);
    }
    float mean = s * (1.0f / 256.0f);
    float var  = ss * (1.0f / 256.0f) - mean * mean;
    float inv  = rsqrtf(var + 1e-5f);
    int c0 = lane * 4, c1 = 128 + lane * 4;
    float o00 = (v0.x - mean) * inv * w[c0+0] + b[c0+0];
    float o01 = (v0.y - mean) * inv * w[c0+1] + b[c0+1];
    float o02 = (v0.z - mean) * inv * w[c0+2] + b[c0+2];
    float o03 = (v0.w - mean) * inv * w[c0+3] + b[c0+3];
    float o10 = (v1.x - mean) * inv * w[c1+0] + b[c1+0];
    float o11 = (v1.y - mean) * inv * w[c1+1] + b[c1+1];
    float o12 = (v1.z - mean) * inv * w[c1+2] + b[c1+2];
    float o13 = (v1.w - mean) * inv * w[c1+3] + b[c1+3];

    size_t drow = row;
    if (mode == 0) {
        int bb = row / (T_*H_*W_);
        int r2 = row % (T_*H_*W_);
        int t = r2 / (H_*W_);
        int r3 = r2 % (H_*W_);
        int h = r3 / W_, ww_ = r3 % W_;
        int t2 = t - STs; if (t2 < 0) t2 += T_;
        int h2 = h - SHs; if (h2 < 0) h2 += H_;
        int w2 = ww_ - SWs; if (w2 < 0) w2 += W_;
        int tw = t2 / WT, hw = h2 / WH, wwn = w2 / WW;
        int n = (t2 % WT) * 49 + (h2 % WH) * 7 + (w2 % WW);
        int bw = ((bb * 4 + tw) * 8 + hw) * 8 + wwn;
        drow = (size_t)bw * N_ + n;
    }
    __nv_bfloat16* dr = dst + drow * 256;
    plain_store4(dr, c0, o00, o01, o02, o03);
    plain_store4(dr, c1, o10, o11, o12, o13);
}

// ---------------- mma.sync GEMM ----------------------------
#define ABUF 18432
#define BUFSZ (2*ABUF)
#define GEMM_SMEM (3*BUFSZ)

template<int EPI>
__global__ __launch_bounds__(256) void gemm_mma(
        const __nv_bfloat16* __restrict__ A, const __nv_bfloat16* __restrict__ Wm,
        const float* __restrict__ bias, const float* __restrict__ resid,
        float* __restrict__ outF, __nv_bfloat16* __restrict__ outB, int K3) {
    extern __shared__ __align__(16) char smraw[];
    int tid = threadIdx.x, lane = tid & 31, wid = tid >> 5;
    int brow = blockIdx.y * 128, bcol = blockIdx.x * 128;
    int wm = wid & 1, wn = wid >> 1;
    uint32_t sb = smem_u32(smraw);

    float acc[4][4][4] = {};
    const int NC = K3 >> 6;

    const char* Agc = (const char*)(A  + (size_t)brow * K3);
    const char* Bgc = (const char*)(Wm + (size_t)bcol * K3);
    size_t rowstride = (size_t)K3 * 2;

    auto loadChunk = [&](int c, int buf) {
        uint32_t abase = sb + buf * BUFSZ;
        uint32_t bbase = abase + ABUF;
        const char* Ag = Agc + (size_t)c * 128;
        const char* Bg = Bgc + (size_t)c * 128;
        #pragma unroll
        for (int j = 0; j < 4; j++) {
            int x = tid + j * 256;
            int row = x >> 3, kc = x & 7;
            CP_ASYNC16(abase + row * 144 + kc * 16, Ag + (size_t)row * rowstride + kc * 16);
            CP_ASYNC16(bbase + row * 144 + kc * 16, Bg + (size_t)row * rowstride + kc * 16);
        }
        CP_COMMIT();
    };

    loadChunk(0, 0);
    if (NC > 1) loadChunk(1, 1);
    int bc = 0, bn2 = 2;
    for (int c = 0; c < NC; c++) {
        if (c + 1 < NC) CP_WAIT1(); else CP_WAIT0();
        __syncthreads();
        if (c + 2 < NC) loadChunk(c + 2, bn2);
        uint32_t abase = sb + bc * BUFSZ;
        uint32_t bbase = abase + ABUF;
        #pragma unroll
        for (int kh = 0; kh < 4; kh++) {
            uint32_t afr[4][4];
            #pragma unroll
            for (int mt = 0; mt < 4; mt++) {
                int row = wm * 64 + mt * 16 + ((lane >> 3) & 1) * 8 + (lane & 7);
                uint32_t addr = abase + row * 144 + kh * 32 + (lane >> 4) * 16;
                LDMATRIX_X4(afr[mt][0], afr[mt][1], afr[mt][2], afr[mt][3], addr);
            }
            uint32_t bfr[4][2];
            #pragma unroll
            for (int np = 0; np < 2; np++) {
                int nrow = wn * 32 + np * 16 + (lane >> 4) * 8 + (lane & 7);
                uint32_t addr = bbase + nrow * 144 + kh * 32 + ((lane >> 3) & 1) * 16;
                uint32_t r0, r1, r2, r3;
                LDMATRIX_X4(r0, r1, r2, r3, addr);
                bfr[np*2][0] = r0; bfr[np*2][1] = r1;
                bfr[np*2+1][0] = r2; bfr[np*2+1][1] = r3;
            }
            #pragma unroll
            for (int mt = 0; mt < 4; mt++)
                #pragma unroll
                for (int nt = 0; nt < 4; nt++)
                    MMA_BF16(acc[mt][nt], afr[mt], bfr[nt]);
        }
        bc++;  if (bc == 3)  bc = 0;
        bn2++; if (bn2 == 3) bn2 = 0;
    }
    __syncthreads();

    float* Cs = (float*)smraw;
    #pragma unroll
    for (int mt = 0; mt < 4; mt++)
        #pragma unroll
        for (int nt = 0; nt < 4; nt++) {
            int r0 = wm * 64 + mt * 16 + (lane >> 2);
            int cc = wn * 32 + nt * 8 + (lane & 3) * 2;
            Cs[r0 * 132 + cc]       = acc[mt][nt][0];
            Cs[r0 * 132 + cc + 1]   = acc[mt][nt][1];
            Cs[(r0+8) * 132 + cc]   = acc[mt][nt][2];
            Cs[(r0+8) * 132 + cc+1] = acc[mt][nt][3];
        }
    __syncthreads();

    float4 bs = *(const float4*)(bias + bcol + lane * 4);
    for (int r = wid; r < 128; r += 8) {
        float4 v = *(const float4*)&Cs[r * 132 + lane * 4];
        v.x += bs.x; v.y += bs.y; v.z += bs.z; v.w += bs.w;
        int grow = brow + r;
        int col = bcol + lane * 4;
        if (EPI == 0) {
            plain_store4(outB + (size_t)grow * 768, col, v.x, v.y, v.z, v.w);
        } else if (EPI == 1) {
            float g0 = 0.5f * v.x * (1.0f + erff(v.x * 0.70710678118654752f));
            float g1 = 0.5f * v.y * (1.0f + erff(v.y * 0.70710678118654752f));
            float g2 = 0.5f * v.z * (1.0f + erff(v.z * 0.70710678118654752f));
            float g3 = 0.5f * v.w * (1.0f + erff(v.w * 0.70710678118654752f));
            plain_store4(outB + (size_t)grow * 1024, col, g0, g1, g2, g3);
        } else if (EPI == 2) {
            int bw = grow / N_, n = grow % N_;
            int bb = bw >> 8, wrem = bw & 255;
            int tw = wrem >> 6, hw = (wrem >> 3) & 7, wwn = wrem & 7;
            int nt = n / 49, nr = n % 49;
            int t2 = tw*WT + nt, h2 = hw*WH + nr/7, w2 = wwn*WW + nr%7;
            int t = t2 + STs; if (t >= T_) t -= T_;
            int h = h2 + SHs; if (h >= H_) h -= H_;
            int ww_ = w2 + SWs; if (ww_ >= W_) ww_ -= W_;
            size_t orow = ((size_t)((bb*T_ + t)*H_ + h))*W_ + ww_;
            float4 rr = *(const float4*)(resid + orow * 256 + col);
            v.x += rr.x; v.y += rr.y; v.z += rr.z; v.w += rr.w;
            *(float4*)(outF + orow * 256 + col) = v;
        } else {
            float4 rr = *(const float4*)(resid + (size_t)grow * 256 + col);
            v.x += rr.x; v.y += rr.y; v.z += rr.z; v.w += rr.w;
            *(float4*)(outF + (size_t)grow * 256 + col) = v;
        }
    }
}

// ---------------- register-resident tensor-core attention ------------------
// QK accs stay in registers; softmax via quad shuffles; P fragments feed AV
// directly (C-fragment layout == A-operand layout); 1/sum applied at output.
#define QSTR 80
#define SM_Q  0
#define SM_K  (112*QSTR)
#define SM_V  (2*112*QSTR)
#define ATTN_SMEM (3*112*QSTR)   // 26880

__global__ __launch_bounds__(128) void attn_tc() {
    extern __shared__ __align__(16) char asmem[];

    int tid = threadIdx.x, lane = tid & 31, wid = tid >> 5;
    int head = blockIdx.x & 7, bw = blockIdx.x >> 3;
    int wrem = bw & 255;
    int tw = wrem >> 6, hw = (wrem >> 3) & 7, wwn = wrem & 7;
    int cat = ((tw == 3) ? 4 : 0) | ((hw == 7) ? 2 : 0) | ((wwn == 7) ? 1 : 0);

    uint32_t uQ = smem_u32(asmem + SM_Q);
    uint32_t uK = smem_u32(asmem + SM_K);
    uint32_t uV = smem_u32(asmem + SM_V);

    if (tid < N_) {
        const uint4* g = (const uint4*)(g_qkv + ((size_t)(bw*N_ + tid)) * 768 + head * HD);
        #pragma unroll
        for (int j = 0; j < 4; j++) {
            *(uint4*)(asmem + SM_Q + tid*QSTR + j*16) = g[j];
            *(uint4*)(asmem + SM_K + tid*QSTR + j*16) = g[32 + j];
            *(uint4*)(asmem + SM_V + tid*QSTR + j*16) = g[64 + j];
        }
    } else if (tid < 112) {
        uint4 z = make_uint4(0,0,0,0);
        #pragma unroll
        for (int j = 0; j < 4; j++) {
            *(uint4*)(asmem + SM_Q + tid*QSTR + j*16) = z;
            *(uint4*)(asmem + SM_K + tid*QSTR + j*16) = z;
            *(uint4*)(asmem + SM_V + tid*QSTR + j*16) = z;
        }
    }
    __syncthreads();

    int nmt = (wid < 3) ? 2 : 1;
    float acc[2][14][4] = {};

    // ---- QK^T into registers ----
    #pragma unroll
    for (int kh = 0; kh < 2; kh++) {
        uint32_t bfr[14][2];
        #pragma unroll
        for (int np = 0; np < 7; np++) {
            int nrow = np*16 + (lane >> 4) * 8 + (lane & 7);
            uint32_t addr = uK + nrow*QSTR + kh*32 + ((lane >> 3) & 1) * 16;
            uint32_t r0, r1, r2, r3;
            LDMATRIX_X4(r0, r1, r2, r3, addr);
            bfr[np*2][0] = r0; bfr[np*2][1] = r1;
            bfr[np*2+1][0] = r2; bfr[np*2+1][1] = r3;
        }
        for (int mtl = 0; mtl < nmt; mtl++) {
            int mt = wid + mtl*4;
            int row = mt*16 + ((lane >> 3) & 1) * 8 + (lane & 7);
            uint32_t addr = uQ + row*QSTR + kh*32 + (lane >> 4) * 16;
            uint32_t afr[4];
            LDMATRIX_X4(afr[0], afr[1], afr[2], afr[3], addr);
            #pragma unroll
            for (int nt = 0; nt < 14; nt++)
                MMA_BF16(acc[mtl][nt], afr, bfr[nt]);
        }
    }

    // ---- register softmax (bias+mask from table; unnormalized exp) ----
    float inv0[2], inv1[2];
    for (int mtl = 0; mtl < nmt; mtl++) {
        int mt = wid + mtl*4;
        int row0 = mt*16 + (lane >> 2);
        const float* bm = g_bm + ((size_t)(cat*8 + head)*112 + row0)*112;
        int c0 = (lane & 3) * 2;
        float mx0 = -1e30f, mx1 = -1e30f;
        #pragma unroll
        for (int nt = 0; nt < 14; nt++) {
            float2 b0 = *(const float2*)(bm + nt*8 + c0);
            float2 b1 = *(const float2*)(bm + 8*112 + nt*8 + c0);
            float s0 = fmaf(acc[mtl][nt][0], 0.17677669529663687f, b0.x);
            float s1 = fmaf(acc[mtl][nt][1], 0.17677669529663687f, b0.y);
            float s2 = fmaf(acc[mtl][nt][2], 0.17677669529663687f, b1.x);
            float s3 = fmaf(acc[mtl][nt][3], 0.17677669529663687f, b1.y);
            acc[mtl][nt][0] = s0; acc[mtl][nt][1] = s1;
            acc[mtl][nt][2] = s2; acc[mtl][nt][3] = s3;
            mx0 = fmaxf(mx0, fmaxf(s0, s1));
            mx1 = fmaxf(mx1, fmaxf(s2, s3));
        }
        mx0 = fmaxf(mx0, __shfl_xor_sync(0xffffffffu, mx0, 1));
        mx0 = fmaxf(mx0, __shfl_xor_sync(0xffffffffu, mx0, 2));
        mx1 = fmaxf(mx1, __shfl_xor_sync(0xffffffffu, mx1, 1));
        mx1 = fmaxf(mx1, __shfl_xor_sync(0xffffffffu, mx1, 2));
        float sm0 = 0.f, sm1 = 0.f;
        #pragma unroll
        for (int nt = 0; nt < 14; nt++) {
            float e0 = __expf(acc[mtl][nt][0] - mx0);
            float e1 = __expf(acc[mtl][nt][1] - mx0);
            float e2 = __expf(acc[mtl][nt][2] - mx1);
            float e3 = __expf(acc[mtl][nt][3] - mx1);
            acc[mtl][nt][0] = e0; acc[mtl][nt][1] = e1;
            acc[mtl][nt][2] = e2; acc[mtl][nt][3] = e3;
            sm0 += e0 + e1; sm1 += e2 + e3;
        }
        sm0 += __shfl_xor_sync(0xffffffffu, sm0, 1);
        sm0 += __shfl_xor_sync(0xffffffffu, sm0, 2);
        sm1 += __shfl_xor_sync(0xffffffffu, sm1, 1);
        sm1 += __shfl_xor_sync(0xffffffffu, sm1, 2);
        inv0[mtl] = 1.0f / sm0;
        inv1[mtl] = 1.0f / sm1;
    }

    // ---- AV: P fragments straight from registers ----
    float av[2][4][4] = {};
    #pragma unroll
    for (int kt = 0; kt < 7; kt++) {
        uint32_t vfr[4][2];
        #pragma unroll
        for (int np = 0; np < 2; np++) {
            int krow = kt*16 + ((lane >> 3) & 1) * 8 + (lane & 7);
            int ncol = np*16 + (lane >> 4) * 8;
            uint32_t addr = uV + krow*QSTR + ncol*2;
            uint32_t r0, r1, r2, r3;
            LDMATRIX_X4T(r0, r1, r2, r3, addr);
            vfr[np*2][0] = r0; vfr[np*2][1] = r1;
            vfr[np*2+1][0] = r2; vfr[np*2+1][1] = r3;
        }
        for (int mtl = 0; mtl < nmt; mtl++) {
            uint32_t pa[4];
            pa[0] = pack2f(acc[mtl][2*kt][0],   acc[mtl][2*kt][1]);
            pa[1] = pack2f(acc[mtl][2*kt][2],   acc[mtl][2*kt][3]);
            pa[2] = pack2f(acc[mtl][2*kt+1][0], acc[mtl][2*kt+1][1]);
            pa[3] = pack2f(acc[mtl][2*kt+1][2], acc[mtl][2*kt+1][3]);
            #pragma unroll
            for (int nt = 0; nt < 4; nt++)
                MMA_BF16(av[mtl][nt], pa, vfr[nt]);
        }
    }

    // ---- store (apply 1/sum here) ----
    for (int mtl = 0; mtl < nmt; mtl++) {
        int mt = wid + mtl*4;
        int r0 = mt*16 + (lane >> 2);
        int cb = head*HD + (lane & 3) * 2;
        #pragma unroll
        for (int nt = 0; nt < 4; nt++) {
            if (r0 < N_)
                *(uint32_t*)(g_att + ((size_t)(bw*N_ + r0))*256 + cb + nt*8)
                    = pack2f(av[mtl][nt][0]*inv0[mtl], av[mtl][nt][1]*inv0[mtl]);
            if (r0 + 8 < N_)
                *(uint32_t*)(g_att + ((size_t)(bw*N_ + r0 + 8))*256 + cb + nt*8)
                    = pack2f(av[mtl][nt][2]*inv1[mtl], av[mtl][nt][3]*inv1[mtl]);
        }
    }
}

// ---------------- host launcher ---------------------------------------------
extern "C" void kernel_launch(void* const* d_in, const int* in_sizes, int n_in,
                              void* d_out, int out_size) {
    const float* x     = (const float*)d_in[0];
    const float* n1w   = (const float*)d_in[1];
    const float* n1b   = (const float*)d_in[2];
    const float* qkvw  = (const float*)d_in[3];
    const float* qkvb  = (const float*)d_in[4];
    const float* projw = (const float*)d_in[5];
    const float* projb = (const float*)d_in[6];
    const float* rpe   = (const float*)d_in[7];
    const float* n2w   = (const float*)d_in[8];
    const float* n2b   = (const float*)d_in[9];
    const float* fc1w  = (const float*)d_in[10];
    const float* fc1b  = (const float*)d_in[11];
    const float* fc2w  = (const float*)d_in[12];
    const float* fc2b  = (const float*)d_in[13];
    float* out = (float*)d_out;

    __nv_bfloat16 *p_xw, *p_qkv, *p_att, *p_hn, *p_h3, *p_wqkv, *p_wproj, *p_wfc1, *p_wfc2;
    float *p_x2;
    cudaGetSymbolAddress((void**)&p_xw,  g_xw);
    cudaGetSymbolAddress((void**)&p_qkv, g_qkv);
    cudaGetSymbolAddress((void**)&p_att, g_att);
    cudaGetSymbolAddress((void**)&p_x2,  g_x2);
    cudaGetSymbolAddress((void**)&p_hn,  g_hn);
    cudaGetSymbolAddress((void**)&p_h3,  g_h3);
    cudaGetSymbolAddress((void**)&p_wqkv,  g_wqkv);
    cudaGetSymbolAddress((void**)&p_wproj, g_wproj);
    cudaGetSymbolAddress((void**)&p_wfc1,  g_wfc1);
    cudaGetSymbolAddress((void**)&p_wfc2,  g_wfc2);

    cudaFuncSetAttribute(attn_tc, cudaFuncAttributeMaxDynamicSharedMemorySize, ATTN_SMEM);
    cudaFuncSetAttribute(gemm_mma<0>, cudaFuncAttributeMaxDynamicSharedMemorySize, GEMM_SMEM);
    cudaFuncSetAttribute(gemm_mma<1>, cudaFuncAttributeMaxDynamicSharedMemorySize, GEMM_SMEM);
    cudaFuncSetAttribute(gemm_mma<2>, cudaFuncAttributeMaxDynamicSharedMemorySize, GEMM_SMEM);
    cudaFuncSetAttribute(gemm_mma<3>, cudaFuncAttributeMaxDynamicSharedMemorySize, GEMM_SMEM);

    // fused setup (weights + bias/mask table)
    setup_kernel<<<(SETUP_ITEMS + 255)/256, 256>>>(qkvw, projw, fc1w, fc2w, rpe);

    // 1. LN1 + roll + window partition -> bf16
    ln_kernel<<<NTOK/8, 256>>>(x, p_xw, n1w, n1b, 0);
    // 2. QKV GEMM (K=256) -> bf16
    gemm_mma<0><<<dim3(6, 392), 256, GEMM_SMEM>>>(p_xw, p_wqkv, qkvb, nullptr, nullptr, p_qkv, 256);
    // 3. register-resident tensor-core attention
    attn_tc<<<BW_*HEADS, 128, ATTN_SMEM>>>();
    // 4. proj GEMM (K=256) + reverse/roll + residual
    gemm_mma<2><<<dim3(2, 392), 256, GEMM_SMEM>>>(p_att, p_wproj, projb, x, p_x2, nullptr, 256);
    // 5. LN2 -> bf16
    ln_kernel<<<NTOK/8, 256>>>(p_x2, p_hn, n2w, n2b, 1);
    // 6. fc1 GEMM (K=256) + GELU -> bf16
    gemm_mma<1><<<dim3(8, 392), 256, GEMM_SMEM>>>(p_hn, p_wfc1, fc1b, nullptr, nullptr, p_h3, 256);
    // 7. fc2 GEMM (K=1024) + residual -> out
    gemm_mma<3><<<dim3(2, 392), 256, GEMM_SMEM>>>(p_h3, p_wfc2, fc2b, p_x2, out, nullptr, 1024);
}